// round 12
// baseline (speedup 1.0000x reference)
#include <cuda_runtime.h>
#include <cuda_fp16.h>
#include <math.h>
#include <stdint.h>

#define PB 4
#define PN 1024
#define PC 768
#define PH 12
#define PD 64
#define PSCALE 0.125f

// ---------------- scratch ----------------
__device__ __half g_xh[(long)PB * PN * PC];
__device__ __half g_wqh[(long)3 * PC * PC];
__device__ __half g_wph[(long)PC * PC];
__device__ __half g_qh[(long)PB * PH * PN * PD];
__device__ __half g_kh[(long)PB * PH * PN * PD];
__device__ __half g_vh[(long)PB * PH * PN * PD];
__device__ __half g_e [(long)PB * PH * PN * PN];   // 100 MB unnormalized exp scores
__device__ float  g_rs[(long)PB * PH * PN];        // row sums
__device__ __half g_oh[(long)PB * PN * PC];

__device__ __forceinline__ uint32_t smem_u32(const void* p) {
    return (uint32_t)__cvta_generic_to_shared(p);
}
__device__ __forceinline__ void cp_async16(uint32_t dst, const void* src) {
    asm volatile("cp.async.cg.shared.global [%0], [%1], 16;" :: "r"(dst), "l"(src));
}
__device__ __forceinline__ void cp_commit() { asm volatile("cp.async.commit_group;"); }
template<int N_> __device__ __forceinline__ void cp_wait() {
    asm volatile("cp.async.wait_group %0;" :: "n"(N_));
}
__device__ __forceinline__ void ldmx4(uint32_t& r0, uint32_t& r1, uint32_t& r2, uint32_t& r3, uint32_t a) {
    asm volatile("ldmatrix.sync.aligned.m8n8.x4.shared.b16 {%0,%1,%2,%3}, [%4];"
                 : "=r"(r0), "=r"(r1), "=r"(r2), "=r"(r3) : "r"(a));
}
__device__ __forceinline__ void ldmx2(uint32_t& r0, uint32_t& r1, uint32_t a) {
    asm volatile("ldmatrix.sync.aligned.m8n8.x2.shared.b16 {%0,%1}, [%2];"
                 : "=r"(r0), "=r"(r1) : "r"(a));
}
__device__ __forceinline__ void ldmx2t(uint32_t& r0, uint32_t& r1, uint32_t a) {
    asm volatile("ldmatrix.sync.aligned.m8n8.x2.trans.shared.b16 {%0,%1}, [%2];"
                 : "=r"(r0), "=r"(r1) : "r"(a));
}
__device__ __forceinline__ void mma_f16(float& c0, float& c1, float& c2, float& c3,
                                        uint32_t a0, uint32_t a1, uint32_t a2, uint32_t a3,
                                        uint32_t b0, uint32_t b1) {
    asm volatile(
        "mma.sync.aligned.m16n8k16.row.col.f32.f16.f16.f32 "
        "{%0,%1,%2,%3}, {%4,%5,%6,%7}, {%8,%9}, {%0,%1,%2,%3};"
        : "+f"(c0), "+f"(c1), "+f"(c2), "+f"(c3)
        : "r"(a0), "r"(a1), "r"(a2), "r"(a3), "r"(b0), "r"(b1));
}
__device__ __forceinline__ float fexp(float x) {   // FMA-pipe exp
    float y = fmaxf(x * 1.4426950408889634f, -80.0f);
    float t = y + 12582912.0f;
    int   n = __float_as_int(t) - 0x4B400000;
    float r = y - (t - 12582912.0f);
    float p = 1.3333558e-3f;
    p = fmaf(p, r, 9.6181291e-3f);
    p = fmaf(p, r, 5.5504109e-2f);
    p = fmaf(p, r, 2.4022651e-1f);
    p = fmaf(p, r, 6.9314718e-1f);
    p = fmaf(p, r, 1.0f);
    return __int_as_float(__float_as_int(p) + (n << 23));
}

// ---------------- fused fp32 -> fp16 converts ----------------
#define N4_X  (PB * PN * PC / 4)
#define N4_WQ (3 * PC * PC / 4)
#define N4_WP (PC * PC / 4)

__global__ void __launch_bounds__(256)
f2h_all(const float* __restrict__ x, const float* __restrict__ wq,
        const float* __restrict__ wp,
        __half* __restrict__ xh, __half* __restrict__ wqh, __half* __restrict__ wph)
{
    int i = blockIdx.x * blockDim.x + threadIdx.x;
    const float* s; __half* d; int j;
    if (i < N4_X)                 { s = x;  d = xh;  j = i; }
    else if (i < N4_X + N4_WQ)    { s = wq; d = wqh; j = i - N4_X; }
    else if (i < N4_X + N4_WQ + N4_WP) { s = wp; d = wph; j = i - N4_X - N4_WQ; }
    else return;
    float4 v = ((const float4*)s)[j];
    ((__half2*)d)[j * 2]     = __floats2half2_rn(v.x, v.y);
    ((__half2*)d)[j * 2 + 1] = __floats2half2_rn(v.z, v.w);
}

// ---------------- fp16 cp.async GEMM, B^T layout (QKV + proj) ----------------
template<int BM, int BN, int BK, int STAGES, int OUTM>
__global__ void __launch_bounds__(256)
gemm_h(const __half* __restrict__ A, const __half* __restrict__ B,
       void* __restrict__ Cb, const float* __restrict__ bias,
       int M, int N, int K, int ldc,
       __half* __restrict__ qp, __half* __restrict__ kp, __half* __restrict__ vp)
{
    constexpr int BKP = BK + 8;
    constexpr int WM = 4, WN = 2;
    constexpr int WTM = BM / WM, WTN = BN / WN;
    constexpr int MT = WTM / 16, NTt = WTN / 8;
    constexpr int ASTG = BM * BKP, BSTG = BN * BKP;
    constexpr int TPR = BK / 8, RPP = 256 / TPR;
    constexpr int APASS = BM / RPP, BPASS = BN / RPP;

    extern __shared__ __half sm[];
    __half* Asm = sm;
    __half* Bsm = sm + (long)STAGES * ASTG;

    const int tid = threadIdx.x, warp = tid >> 5, lane = tid & 31;
    const int g = lane >> 2, c4 = lane & 3;
    const int wm = warp % WM, wn = warp / WM;
    const int m0 = blockIdx.y * BM, n0 = blockIdx.x * BN;

    float acc[MT][NTt][4];
    #pragma unroll
    for (int i = 0; i < MT; i++)
        #pragma unroll
        for (int j = 0; j < NTt; j++)
            #pragma unroll
            for (int r = 0; r < 4; r++) acc[i][j][r] = 0.0f;

    const int nk = K / BK;
    auto load_stage = [&](int st, int k0) {
        const int r = tid / TPR, kc = (tid % TPR) * 8;
        #pragma unroll
        for (int p = 0; p < APASS; p++)
            cp_async16(smem_u32(Asm + (long)st * ASTG + (r + p * RPP) * BKP + kc),
                       A + (long)(m0 + r + p * RPP) * K + k0 + kc);
        #pragma unroll
        for (int p = 0; p < BPASS; p++)
            cp_async16(smem_u32(Bsm + (long)st * BSTG + (r + p * RPP) * BKP + kc),
                       B + (long)(n0 + r + p * RPP) * K + k0 + kc);
    };
    auto compute_stage = [&](int st) {
        const __half* As = Asm + (long)st * ASTG;
        const __half* Bs = Bsm + (long)st * BSTG;
        #pragma unroll
        for (int kk = 0; kk < BK; kk += 16) {
            uint32_t afr[MT][4];
            #pragma unroll
            for (int mt = 0; mt < MT; mt++)
                ldmx4(afr[mt][0], afr[mt][1], afr[mt][2], afr[mt][3],
                      smem_u32(As + (wm * WTM + mt * 16 + (lane & 15)) * BKP + kk + ((lane >> 4) << 3)));
            uint32_t bfr[NTt][2];
            #pragma unroll
            for (int nt = 0; nt < NTt; nt++)
                ldmx2(bfr[nt][0], bfr[nt][1],
                      smem_u32(Bs + (wn * WTN + nt * 8 + (lane & 7)) * BKP + kk + (((lane >> 3) & 1) << 3)));
            #pragma unroll
            for (int mt = 0; mt < MT; mt++)
                #pragma unroll
                for (int nt = 0; nt < NTt; nt++)
                    mma_f16(acc[mt][nt][0], acc[mt][nt][1], acc[mt][nt][2], acc[mt][nt][3],
                            afr[mt][0], afr[mt][1], afr[mt][2], afr[mt][3],
                            bfr[nt][0], bfr[nt][1]);
        }
    };

    #pragma unroll
    for (int s = 0; s < STAGES - 1; s++) {
        if (s < nk) load_stage(s, s * BK);
        cp_commit();
    }
    for (int i = 0; i < nk; i++) {
        cp_wait<STAGES - 2>();
        __syncthreads();
        compute_stage(i % STAGES);
        const int nx = i + STAGES - 1;
        if (nx < nk) load_stage(nx % STAGES, nx * BK);
        cp_commit();
        __syncthreads();
    }

    if constexpr (OUTM == 0) {
        float* C = (float*)Cb;
        #pragma unroll
        for (int mt = 0; mt < MT; mt++) {
            const int row = m0 + wm * WTM + mt * 16 + g;
            #pragma unroll
            for (int nt = 0; nt < NTt; nt++) {
                const int col = n0 + wn * WTN + nt * 8 + c4 * 2;
                float b0 = 0.0f, b1 = 0.0f;
                if (bias) { b0 = bias[col]; b1 = bias[col + 1]; }
                *(float2*)(C + (long)row * ldc + col) =
                    make_float2(acc[mt][nt][0] + b0, acc[mt][nt][1] + b1);
                *(float2*)(C + (long)(row + 8) * ldc + col) =
                    make_float2(acc[mt][nt][2] + b0, acc[mt][nt][3] + b1);
            }
        }
    } else {
        #pragma unroll
        for (int mt = 0; mt < MT; mt++) {
            const int row = m0 + wm * WTM + mt * 16 + g;
            const int b = row >> 10, n = row & 1023;
            #pragma unroll
            for (int nt = 0; nt < NTt; nt++) {
                const int col = n0 + wn * WTN + nt * 8 + c4 * 2;
                const int s = col / PC, r2 = col % PC;
                const int h = r2 >> 6, d = r2 & 63;
                __half* dstb = (s == 0) ? qp : (s == 1) ? kp : vp;
                const float sc = (s == 0) ? PSCALE : 1.0f;
                const long base = (((long)(b * PH + h) << 10) + n) * PD + d;
                *(__half2*)(dstb + base) = __floats2half2_rn(acc[mt][nt][0] * sc, acc[mt][nt][1] * sc);
                *(__half2*)(dstb + base + 8L * PD) = __floats2half2_rn(acc[mt][nt][2] * sc, acc[mt][nt][3] * sc);
            }
        }
    }
}

// ---------------- Stage 1: QK + pre-mix + exp + row sums (unchanged) ----------------
#define S1_K0 55296
#define S1_E  165888
#define S1_SM 190464

__global__ void __launch_bounds__(256)
qk_exp(const __half* __restrict__ qh, const __half* __restrict__ kh,
       __half* __restrict__ eG, float* __restrict__ rsG,
       const float* __restrict__ W_l, const float* __restrict__ b_l)
{
    extern __shared__ char dyn[];
    __half* qT = (__half*)dyn;
    __half* kB[2] = { (__half*)(dyn + S1_K0), (__half*)(dyn + 2 * S1_K0) };
    __half* eS = (__half*)(dyn + S1_E);
    __shared__ float wl[144], bls[12];
    __shared__ float rs[12][32];

    const int tid = threadIdx.x, warp = tid >> 5, lane = tid & 31;
    const int c4 = lane & 3, r8 = lane >> 2;
    const int wA = warp & 3, wN = warp >> 2;
    const int n0 = blockIdx.x * 32, b = blockIdx.y;

    if (tid < 144) wl[tid] = W_l[tid];
    if (tid < 12)  bls[tid] = b_l[tid];
    for (int t = tid; t < 384; t += 256) ((float*)rs)[t] = 0.0f;

    #pragma unroll
    for (int it = 0; it < 12; it++) {
        int c = it * 256 + tid, h = c >> 8, rr = (c >> 3) & 31, cc = (c & 7) * 8;
        cp_async16(smem_u32(qT + (h * 32 + rr) * 72 + cc),
                   qh + (((long)(b * PH + h) << 10) + n0 + rr) * PD + cc);
    }
    cp_commit();

    auto loadk = [&](int mt, __half* buf) {
        #pragma unroll
        for (int it = 0; it < 12; it++) {
            int c = it * 256 + tid, h = c >> 8, rr = (c >> 3) & 31, cc = (c & 7) * 8;
            cp_async16(smem_u32(buf + (h * 32 + rr) * 72 + cc),
                       kh + (((long)(b * PH + h) << 10) + mt * 32 + rr) * PD + cc);
        }
    };
    loadk(0, kB[0]); cp_commit();

    float ps[12][2];
    #pragma unroll
    for (int g = 0; g < 12; g++) { ps[g][0] = 0.0f; ps[g][1] = 0.0f; }

    for (int mt = 0; mt < 32; mt++) {
        __half* cur = kB[mt & 1];
        if (mt + 1 < 32) { loadk(mt + 1, kB[(mt + 1) & 1]); cp_commit(); cp_wait<1>(); }
        else             { cp_wait<0>(); }
        __syncthreads();

        float acc[12][4];
        #pragma unroll
        for (int h = 0; h < 12; h++)
            #pragma unroll
            for (int r = 0; r < 4; r++) acc[h][r] = 0.0f;
        #pragma unroll
        for (int h = 0; h < 12; h++) {
            #pragma unroll
            for (int kc = 0; kc < 4; kc++) {
                uint32_t a0, a1, a2, a3, b0, b1;
                ldmx4(a0, a1, a2, a3,
                      smem_u32(qT + (h * 32 + wN * 16 + (lane & 15)) * 72 + kc * 16 + ((lane >> 4) << 3)));
                ldmx2(b0, b1,
                      smem_u32(cur + (h * 32 + wA * 8 + (lane & 7)) * 72 + kc * 16 + (((lane >> 3) & 1) << 3)));
                mma_f16(acc[h][0], acc[h][1], acc[h][2], acc[h][3], a0, a1, a2, a3, b0, b1);
            }
        }
        #pragma unroll
        for (int g = 0; g < 12; g++) {
            float t0 = bls[g], t1 = t0, t2 = t0, t3 = t0;
            #pragma unroll
            for (int h = 0; h < 12; h++) {
                const float w = wl[g * 12 + h];
                t0 = fmaf(w, acc[h][0], t0); t1 = fmaf(w, acc[h][1], t1);
                t2 = fmaf(w, acc[h][2], t2); t3 = fmaf(w, acc[h][3], t3);
            }
            const float e0 = fexp(t0), e1 = fexp(t1), e2 = fexp(t2), e3 = fexp(t3);
            ps[g][0] += e0 + e1; ps[g][1] += e2 + e3;
            const int mcol = wA * 8 + c4 * 2;
            *(__half2*)(eS + (g * 32 + wN * 16 + r8) * 32 + mcol)     = __floats2half2_rn(e0, e1);
            *(__half2*)(eS + (g * 32 + wN * 16 + r8 + 8) * 32 + mcol) = __floats2half2_rn(e2, e3);
        }
        __syncthreads();
        #pragma unroll
        for (int j = 0; j < 6; j++) {
            int c = tid + j * 256, h = c >> 7, nn = (c >> 2) & 31, q4 = c & 3;
            float4 v = *(float4*)(eS + (h * 32 + nn) * 32 + q4 * 8);
            *(float4*)(eG + ((long)(b * PH + h) << 20) + ((long)(n0 + nn) << 10) + mt * 32 + q4 * 8) = v;
        }
    }
    #pragma unroll
    for (int g = 0; g < 12; g++)
        #pragma unroll
        for (int q = 0; q < 2; q++) {
            ps[g][q] += __shfl_xor_sync(0xFFFFFFFFu, ps[g][q], 1);
            ps[g][q] += __shfl_xor_sync(0xFFFFFFFFu, ps[g][q], 2);
        }
    __syncthreads();
    if (c4 == 0) {
        #pragma unroll
        for (int g = 0; g < 12; g++) {
            atomicAdd(&rs[g][wN * 16 + r8],     ps[g][0]);
            atomicAdd(&rs[g][wN * 16 + r8 + 8], ps[g][1]);
        }
    }
    __syncthreads();
    for (int t = tid; t < 384; t += 256) {
        int h = t >> 5, nn = t & 31;
        rsG[((long)(b * PH + h) << 10) + n0 + nn] = rs[h][nn];
    }
}

// ---------------- Stage 2: warp-per-head normalize + post-mix + PV ----------------
// 384 threads = 12 warps; warp h owns head h in the PV phase.
// smem: eB double [12][32][40], aS [12][32][40], vB double [12][32][72]
#define S2_EB  30720
#define S2_AS  61440
#define S2_V0  92160
#define S2_VST 55296
#define S2_SM  202752

__global__ void __launch_bounds__(384)
mix_pv(const __half* __restrict__ eG, const __half* __restrict__ vh,
       const float* __restrict__ rsG, __half* __restrict__ oh,
       const float* __restrict__ W_w, const float* __restrict__ b_w,
       const float* __restrict__ lamb)
{
    extern __shared__ char dyn[];
    __half* eB[2] = { (__half*)dyn, (__half*)(dyn + S2_EB) };
    __half* aS   = (__half*)(dyn + S2_AS);
    __half* vB[2] = { (__half*)(dyn + S2_V0), (__half*)(dyn + S2_V0 + S2_VST) };
    __shared__ float wp[144], cg[12], invS[12][32];

    const int tid = threadIdx.x, warp = tid >> 5, lane = tid & 31;
    const int c4 = lane & 3, r8 = lane >> 2;
    const int n0 = blockIdx.x * 32, b = blockIdx.y;
    const int h = warp;                        // warp-per-head

    if (tid < 144) wp[tid] = W_w[tid] * (1.0f + lamb[tid / 12]);
    if (tid < 12) { const float ad = 1.0f / 1024.0f; cg[tid] = ad + (b_w[tid] - ad) * (1.0f + lamb[tid]); }
    if (tid < 384) {
        int hh = tid >> 5, nn = tid & 31;
        invS[hh][nn] = 1.0f / rsG[((long)(b * PH + hh) << 10) + n0 + nn];
    }

    auto loadE = [&](int mt, __half* buf) {
        #pragma unroll
        for (int c = tid; c < 1536; c += 384) {          // 12*32*4 chunks of 8 halves
            int hh = c >> 7, nn = (c >> 2) & 31, q4 = c & 3;
            cp_async16(smem_u32(buf + (hh * 32 + nn) * 40 + q4 * 8),
                       eG + ((long)(b * PH + hh) << 20) + ((long)(n0 + nn) << 10) + mt * 32 + q4 * 8);
        }
    };
    auto loadV = [&](int mt, __half* buf) {
        #pragma unroll
        for (int c = tid; c < 3072; c += 384) {          // 12*32*8 chunks of 8 halves
            int hh = c >> 8, rr = (c >> 3) & 31, cc = (c & 7) * 8;
            cp_async16(smem_u32(buf + (hh * 32 + rr) * 72 + cc),
                       vh + (((long)(b * PH + hh) << 10) + mt * 32 + rr) * PD + cc);
        }
    };

    float acc[2][8][4];                        // rows 2x16, d 8x8 for this warp's head
    #pragma unroll
    for (int f = 0; f < 2; f++)
        #pragma unroll
        for (int nt = 0; nt < 8; nt++)
            #pragma unroll
            for (int r = 0; r < 4; r++) acc[f][nt][r] = 0.0f;

    loadE(0, eB[0]); loadV(0, vB[0]); cp_commit();

    for (int mt = 0; mt < 32; mt++) {
        __half* ec = eB[mt & 1];
        __half* vc = vB[mt & 1];
        if (mt + 1 < 32) { loadE(mt + 1, eB[(mt + 1) & 1]); loadV(mt + 1, vB[(mt + 1) & 1]); cp_commit(); cp_wait<1>(); }
        else             { cp_wait<0>(); }
        __syncthreads();   // data ready; prior iter's PV reads of aS done

        // mix: all 384 threads cover 1024 points
        for (int p = tid; p < 1024; p += 384) {
            const int nn = p >> 5, m = p & 31;
            float f[12];
            #pragma unroll
            for (int hh = 0; hh < 12; hh++)
                f[hh] = __half2float(ec[(hh * 32 + nn) * 40 + m]) * invS[hh][nn];
            #pragma unroll
            for (int g = 0; g < 12; g++) {
                float a = cg[g];
                #pragma unroll
                for (int hh = 0; hh < 12; hh++) a = fmaf(wp[g * 12 + hh], f[hh], a);
                aS[(g * 32 + nn) * 40 + m] = __float2half_rn(a);
            }
        }
        __syncthreads();   // aS ready

        // PV: warp h computes O[h] tile
        #pragma unroll
        for (int kc = 0; kc < 2; kc++) {
            uint32_t bfr[8][2];
            #pragma unroll
            for (int nt = 0; nt < 8; nt++)
                ldmx2t(bfr[nt][0], bfr[nt][1],
                       smem_u32(vc + (h * 32 + kc * 16 + (lane & 15)) * 72 + nt * 8));
            #pragma unroll
            for (int f = 0; f < 2; f++) {
                uint32_t a0, a1, a2, a3;
                ldmx4(a0, a1, a2, a3,
                      smem_u32(aS + (h * 32 + f * 16 + (lane & 15)) * 40 + kc * 16 + ((lane >> 4) << 3)));
                #pragma unroll
                for (int nt = 0; nt < 8; nt++)
                    mma_f16(acc[f][nt][0], acc[f][nt][1], acc[f][nt][2], acc[f][nt][3],
                            a0, a1, a2, a3, bfr[nt][0], bfr[nt][1]);
            }
        }
        __syncthreads();   // PV reads done before next iter's writes
    }

    #pragma unroll
    for (int f = 0; f < 2; f++)
        #pragma unroll
        for (int nt = 0; nt < 8; nt++) {
            const long base = ((long)((b << 10) + n0 + f * 16 + r8)) * PC + h * 64 + nt * 8 + c4 * 2;
            *(__half2*)(oh + base)           = __floats2half2_rn(acc[f][nt][0], acc[f][nt][1]);
            *(__half2*)(oh + base + 8L * PC) = __floats2half2_rn(acc[f][nt][2], acc[f][nt][3]);
        }
}

// ---------------- launcher ----------------
extern "C" void kernel_launch(void* const* d_in, const int* in_sizes, int n_in,
                              void* d_out, int out_size)
{
    const float* x      = (const float*)d_in[0];
    const float* W_qkv  = (const float*)d_in[1];
    const float* W_proj = (const float*)d_in[2];
    const float* b_proj = (const float*)d_in[3];
    const float* W_l    = (const float*)d_in[4];
    const float* b_l    = (const float*)d_in[5];
    const float* W_w    = (const float*)d_in[6];
    const float* b_w    = (const float*)d_in[7];
    const float* lamb   = (const float*)d_in[8];
    float* out = (float*)d_out;

    __half *xh, *wqh, *wph, *qh, *kh, *vh, *e, *oh;
    float *rs;
    cudaGetSymbolAddress((void**)&xh,  g_xh);
    cudaGetSymbolAddress((void**)&wqh, g_wqh);
    cudaGetSymbolAddress((void**)&wph, g_wph);
    cudaGetSymbolAddress((void**)&qh,  g_qh);
    cudaGetSymbolAddress((void**)&kh,  g_kh);
    cudaGetSymbolAddress((void**)&vh,  g_vh);
    cudaGetSymbolAddress((void**)&e,   g_e);
    cudaGetSymbolAddress((void**)&rs,  g_rs);
    cudaGetSymbolAddress((void**)&oh,  g_oh);

    const int M = PB * PN;
    constexpr int SM_G = 3 * 2 * 128 * 72 * 2;   // 110592 (BK=64, 3 stages)

    {   const int total = N4_X + N4_WQ + N4_WP;
        f2h_all<<<(total + 255) / 256, 256>>>(x, W_qkv, W_proj, xh, wqh, wph);
    }
    {   auto kfn = gemm_h<128, 128, 64, 3, 2>;
        cudaFuncSetAttribute(kfn, cudaFuncAttributeMaxDynamicSharedMemorySize, SM_G);
        dim3 grid(3 * PC / 128, M / 128, 1);
        kfn<<<grid, 256, SM_G>>>(xh, wqh, nullptr, nullptr, M, 3 * PC, PC, 0, qh, kh, vh);
    }
    {   cudaFuncSetAttribute(qk_exp, cudaFuncAttributeMaxDynamicSharedMemorySize, S1_SM);
        dim3 grid(PN / 32, PB, 1);
        qk_exp<<<grid, 256, S1_SM>>>(qh, kh, e, rs, W_l, b_l);
    }
    {   cudaFuncSetAttribute(mix_pv, cudaFuncAttributeMaxDynamicSharedMemorySize, S2_SM);
        dim3 grid(PN / 32, PB, 1);
        mix_pv<<<grid, 384, S2_SM>>>(e, vh, rs, oh, W_w, b_w, lamb);
    }
    {   auto kfn = gemm_h<128, 128, 64, 3, 0>;
        cudaFuncSetAttribute(kfn, cudaFuncAttributeMaxDynamicSharedMemorySize, SM_G);
        dim3 grid(PC / 128, M / 128, 1);
        kfn<<<grid, 256, SM_G>>>(oh, wph, out, b_proj, M, PC, PC, PC, nullptr, nullptr, nullptr);
    }
}

// round 13
// speedup vs baseline: 1.2510x; 1.2510x over previous
#include <cuda_runtime.h>
#include <cuda_fp16.h>
#include <math.h>
#include <stdint.h>

#define PB 4
#define PN 1024
#define PC 768
#define PH 12
#define PD 64
#define PSCALE 0.125f

// ---------------- scratch ----------------
__device__ __half g_xh[(long)PB * PN * PC];
__device__ __half g_wqh[(long)3 * PC * PC];
__device__ __half g_wph[(long)PC * PC];
__device__ __half g_qh[(long)PB * PH * PN * PD];
__device__ __half g_kh[(long)PB * PH * PN * PD];
__device__ __half g_vh[(long)PB * PH * PN * PD];
__device__ __half g_e [(long)PB * PH * PN * PN];   // 100 MB unnormalized exp scores
__device__ float  g_rs[(long)PB * PH * PN];        // row sums
__device__ __half g_oh[(long)PB * PN * PC];

__device__ __forceinline__ uint32_t smem_u32(const void* p) {
    return (uint32_t)__cvta_generic_to_shared(p);
}
__device__ __forceinline__ void cp_async16(uint32_t dst, const void* src) {
    asm volatile("cp.async.cg.shared.global [%0], [%1], 16;" :: "r"(dst), "l"(src));
}
__device__ __forceinline__ void cp_commit() { asm volatile("cp.async.commit_group;"); }
template<int N_> __device__ __forceinline__ void cp_wait() {
    asm volatile("cp.async.wait_group %0;" :: "n"(N_));
}
__device__ __forceinline__ void ldmx4(uint32_t& r0, uint32_t& r1, uint32_t& r2, uint32_t& r3, uint32_t a) {
    asm volatile("ldmatrix.sync.aligned.m8n8.x4.shared.b16 {%0,%1,%2,%3}, [%4];"
                 : "=r"(r0), "=r"(r1), "=r"(r2), "=r"(r3) : "r"(a));
}
__device__ __forceinline__ void ldmx2(uint32_t& r0, uint32_t& r1, uint32_t a) {
    asm volatile("ldmatrix.sync.aligned.m8n8.x2.shared.b16 {%0,%1}, [%2];"
                 : "=r"(r0), "=r"(r1) : "r"(a));
}
__device__ __forceinline__ void ldmx2t(uint32_t& r0, uint32_t& r1, uint32_t a) {
    asm volatile("ldmatrix.sync.aligned.m8n8.x2.trans.shared.b16 {%0,%1}, [%2];"
                 : "=r"(r0), "=r"(r1) : "r"(a));
}
__device__ __forceinline__ void mma_f16(float& c0, float& c1, float& c2, float& c3,
                                        uint32_t a0, uint32_t a1, uint32_t a2, uint32_t a3,
                                        uint32_t b0, uint32_t b1) {
    asm volatile(
        "mma.sync.aligned.m16n8k16.row.col.f32.f16.f16.f32 "
        "{%0,%1,%2,%3}, {%4,%5,%6,%7}, {%8,%9}, {%0,%1,%2,%3};"
        : "+f"(c0), "+f"(c1), "+f"(c2), "+f"(c3)
        : "r"(a0), "r"(a1), "r"(a2), "r"(a3), "r"(b0), "r"(b1));
}
__device__ __forceinline__ float fexp(float x) {   // FMA-pipe exp
    float y = fmaxf(x * 1.4426950408889634f, -80.0f);
    float t = y + 12582912.0f;
    int   n = __float_as_int(t) - 0x4B400000;
    float r = y - (t - 12582912.0f);
    float p = 1.3333558e-3f;
    p = fmaf(p, r, 9.6181291e-3f);
    p = fmaf(p, r, 5.5504109e-2f);
    p = fmaf(p, r, 2.4022651e-1f);
    p = fmaf(p, r, 6.9314718e-1f);
    p = fmaf(p, r, 1.0f);
    return __int_as_float(__float_as_int(p) + (n << 23));
}

// ---------------- fused fp32 -> fp16 converts ----------------
#define N4_X  (PB * PN * PC / 4)
#define N4_WQ (3 * PC * PC / 4)
#define N4_WP (PC * PC / 4)

__global__ void __launch_bounds__(256)
f2h_all(const float* __restrict__ x, const float* __restrict__ wq,
        const float* __restrict__ wp,
        __half* __restrict__ xh, __half* __restrict__ wqh, __half* __restrict__ wph)
{
    int i = blockIdx.x * blockDim.x + threadIdx.x;
    const float* s; __half* d; int j;
    if (i < N4_X)                 { s = x;  d = xh;  j = i; }
    else if (i < N4_X + N4_WQ)    { s = wq; d = wqh; j = i - N4_X; }
    else if (i < N4_X + N4_WQ + N4_WP) { s = wp; d = wph; j = i - N4_X - N4_WQ; }
    else return;
    float4 v = ((const float4*)s)[j];
    ((__half2*)d)[j * 2]     = __floats2half2_rn(v.x, v.y);
    ((__half2*)d)[j * 2 + 1] = __floats2half2_rn(v.z, v.w);
}

// ---------------- fp16 cp.async GEMM, B^T layout (QKV + proj) ----------------
template<int BM, int BN, int BK, int STAGES, int OUTM>
__global__ void __launch_bounds__(256)
gemm_h(const __half* __restrict__ A, const __half* __restrict__ B,
       void* __restrict__ Cb, const float* __restrict__ bias,
       int M, int N, int K, int ldc,
       __half* __restrict__ qp, __half* __restrict__ kp, __half* __restrict__ vp)
{
    constexpr int BKP = BK + 8;
    constexpr int WM = 4, WN = 2;
    constexpr int WTM = BM / WM, WTN = BN / WN;
    constexpr int MT = WTM / 16, NTt = WTN / 8;
    constexpr int ASTG = BM * BKP, BSTG = BN * BKP;
    constexpr int TPR = BK / 8, RPP = 256 / TPR;
    constexpr int APASS = BM / RPP, BPASS = BN / RPP;

    extern __shared__ __half sm[];
    __half* Asm = sm;
    __half* Bsm = sm + (long)STAGES * ASTG;

    const int tid = threadIdx.x, warp = tid >> 5, lane = tid & 31;
    const int g = lane >> 2, c4 = lane & 3;
    const int wm = warp % WM, wn = warp / WM;
    const int m0 = blockIdx.y * BM, n0 = blockIdx.x * BN;

    float acc[MT][NTt][4];
    #pragma unroll
    for (int i = 0; i < MT; i++)
        #pragma unroll
        for (int j = 0; j < NTt; j++)
            #pragma unroll
            for (int r = 0; r < 4; r++) acc[i][j][r] = 0.0f;

    const int nk = K / BK;
    auto load_stage = [&](int st, int k0) {
        const int r = tid / TPR, kc = (tid % TPR) * 8;
        #pragma unroll
        for (int p = 0; p < APASS; p++)
            cp_async16(smem_u32(Asm + (long)st * ASTG + (r + p * RPP) * BKP + kc),
                       A + (long)(m0 + r + p * RPP) * K + k0 + kc);
        #pragma unroll
        for (int p = 0; p < BPASS; p++)
            cp_async16(smem_u32(Bsm + (long)st * BSTG + (r + p * RPP) * BKP + kc),
                       B + (long)(n0 + r + p * RPP) * K + k0 + kc);
    };
    auto compute_stage = [&](int st) {
        const __half* As = Asm + (long)st * ASTG;
        const __half* Bs = Bsm + (long)st * BSTG;
        #pragma unroll
        for (int kk = 0; kk < BK; kk += 16) {
            uint32_t afr[MT][4];
            #pragma unroll
            for (int mt = 0; mt < MT; mt++)
                ldmx4(afr[mt][0], afr[mt][1], afr[mt][2], afr[mt][3],
                      smem_u32(As + (wm * WTM + mt * 16 + (lane & 15)) * BKP + kk + ((lane >> 4) << 3)));
            uint32_t bfr[NTt][2];
            #pragma unroll
            for (int nt = 0; nt < NTt; nt++)
                ldmx2(bfr[nt][0], bfr[nt][1],
                      smem_u32(Bs + (wn * WTN + nt * 8 + (lane & 7)) * BKP + kk + (((lane >> 3) & 1) << 3)));
            #pragma unroll
            for (int mt = 0; mt < MT; mt++)
                #pragma unroll
                for (int nt = 0; nt < NTt; nt++)
                    mma_f16(acc[mt][nt][0], acc[mt][nt][1], acc[mt][nt][2], acc[mt][nt][3],
                            afr[mt][0], afr[mt][1], afr[mt][2], afr[mt][3],
                            bfr[nt][0], bfr[nt][1]);
        }
    };

    #pragma unroll
    for (int s = 0; s < STAGES - 1; s++) {
        if (s < nk) load_stage(s, s * BK);
        cp_commit();
    }
    for (int i = 0; i < nk; i++) {
        cp_wait<STAGES - 2>();
        __syncthreads();
        compute_stage(i % STAGES);
        const int nx = i + STAGES - 1;
        if (nx < nk) load_stage(nx % STAGES, nx * BK);
        cp_commit();
        __syncthreads();
    }

    if constexpr (OUTM == 0) {
        float* C = (float*)Cb;
        #pragma unroll
        for (int mt = 0; mt < MT; mt++) {
            const int row = m0 + wm * WTM + mt * 16 + g;
            #pragma unroll
            for (int nt = 0; nt < NTt; nt++) {
                const int col = n0 + wn * WTN + nt * 8 + c4 * 2;
                float b0 = 0.0f, b1 = 0.0f;
                if (bias) { b0 = bias[col]; b1 = bias[col + 1]; }
                *(float2*)(C + (long)row * ldc + col) =
                    make_float2(acc[mt][nt][0] + b0, acc[mt][nt][1] + b1);
                *(float2*)(C + (long)(row + 8) * ldc + col) =
                    make_float2(acc[mt][nt][2] + b0, acc[mt][nt][3] + b1);
            }
        }
    } else {
        #pragma unroll
        for (int mt = 0; mt < MT; mt++) {
            const int row = m0 + wm * WTM + mt * 16 + g;
            const int b = row >> 10, n = row & 1023;
            #pragma unroll
            for (int nt = 0; nt < NTt; nt++) {
                const int col = n0 + wn * WTN + nt * 8 + c4 * 2;
                const int s = col / PC, r2 = col % PC;
                const int h = r2 >> 6, d = r2 & 63;
                __half* dstb = (s == 0) ? qp : (s == 1) ? kp : vp;
                const float sc = (s == 0) ? PSCALE : 1.0f;
                const long base = (((long)(b * PH + h) << 10) + n) * PD + d;
                *(__half2*)(dstb + base) = __floats2half2_rn(acc[mt][nt][0] * sc, acc[mt][nt][1] * sc);
                *(__half2*)(dstb + base + 8L * PD) = __floats2half2_rn(acc[mt][nt][2] * sc, acc[mt][nt][3] * sc);
            }
        }
    }
}

// ---------------- Stage 1: QK + pre-mix + exp + row sums (unchanged) ----------------
#define S1_K0 55296
#define S1_E  165888
#define S1_SM 190464

__global__ void __launch_bounds__(256)
qk_exp(const __half* __restrict__ qh, const __half* __restrict__ kh,
       __half* __restrict__ eG, float* __restrict__ rsG,
       const float* __restrict__ W_l, const float* __restrict__ b_l)
{
    extern __shared__ char dyn[];
    __half* qT = (__half*)dyn;
    __half* kB[2] = { (__half*)(dyn + S1_K0), (__half*)(dyn + 2 * S1_K0) };
    __half* eS = (__half*)(dyn + S1_E);
    __shared__ float wl[144], bls[12];
    __shared__ float rs[12][32];

    const int tid = threadIdx.x, warp = tid >> 5, lane = tid & 31;
    const int c4 = lane & 3, r8 = lane >> 2;
    const int wA = warp & 3, wN = warp >> 2;
    const int n0 = blockIdx.x * 32, b = blockIdx.y;

    if (tid < 144) wl[tid] = W_l[tid];
    if (tid < 12)  bls[tid] = b_l[tid];
    for (int t = tid; t < 384; t += 256) ((float*)rs)[t] = 0.0f;

    #pragma unroll
    for (int it = 0; it < 12; it++) {
        int c = it * 256 + tid, h = c >> 8, rr = (c >> 3) & 31, cc = (c & 7) * 8;
        cp_async16(smem_u32(qT + (h * 32 + rr) * 72 + cc),
                   qh + (((long)(b * PH + h) << 10) + n0 + rr) * PD + cc);
    }
    cp_commit();

    auto loadk = [&](int mt, __half* buf) {
        #pragma unroll
        for (int it = 0; it < 12; it++) {
            int c = it * 256 + tid, h = c >> 8, rr = (c >> 3) & 31, cc = (c & 7) * 8;
            cp_async16(smem_u32(buf + (h * 32 + rr) * 72 + cc),
                       kh + (((long)(b * PH + h) << 10) + mt * 32 + rr) * PD + cc);
        }
    };
    loadk(0, kB[0]); cp_commit();

    float ps[12][2];
    #pragma unroll
    for (int g = 0; g < 12; g++) { ps[g][0] = 0.0f; ps[g][1] = 0.0f; }

    for (int mt = 0; mt < 32; mt++) {
        __half* cur = kB[mt & 1];
        if (mt + 1 < 32) { loadk(mt + 1, kB[(mt + 1) & 1]); cp_commit(); cp_wait<1>(); }
        else             { cp_wait<0>(); }
        __syncthreads();

        float acc[12][4];
        #pragma unroll
        for (int h = 0; h < 12; h++)
            #pragma unroll
            for (int r = 0; r < 4; r++) acc[h][r] = 0.0f;
        #pragma unroll
        for (int h = 0; h < 12; h++) {
            #pragma unroll
            for (int kc = 0; kc < 4; kc++) {
                uint32_t a0, a1, a2, a3, b0, b1;
                ldmx4(a0, a1, a2, a3,
                      smem_u32(qT + (h * 32 + wN * 16 + (lane & 15)) * 72 + kc * 16 + ((lane >> 4) << 3)));
                ldmx2(b0, b1,
                      smem_u32(cur + (h * 32 + wA * 8 + (lane & 7)) * 72 + kc * 16 + (((lane >> 3) & 1) << 3)));
                mma_f16(acc[h][0], acc[h][1], acc[h][2], acc[h][3], a0, a1, a2, a3, b0, b1);
            }
        }
        #pragma unroll
        for (int g = 0; g < 12; g++) {
            float t0 = bls[g], t1 = t0, t2 = t0, t3 = t0;
            #pragma unroll
            for (int h = 0; h < 12; h++) {
                const float w = wl[g * 12 + h];
                t0 = fmaf(w, acc[h][0], t0); t1 = fmaf(w, acc[h][1], t1);
                t2 = fmaf(w, acc[h][2], t2); t3 = fmaf(w, acc[h][3], t3);
            }
            const float e0 = fexp(t0), e1 = fexp(t1), e2 = fexp(t2), e3 = fexp(t3);
            ps[g][0] += e0 + e1; ps[g][1] += e2 + e3;
            const int mcol = wA * 8 + c4 * 2;
            *(__half2*)(eS + (g * 32 + wN * 16 + r8) * 32 + mcol)     = __floats2half2_rn(e0, e1);
            *(__half2*)(eS + (g * 32 + wN * 16 + r8 + 8) * 32 + mcol) = __floats2half2_rn(e2, e3);
        }
        __syncthreads();
        #pragma unroll
        for (int j = 0; j < 6; j++) {
            int c = tid + j * 256, h = c >> 7, nn = (c >> 2) & 31, q4 = c & 3;
            float4 v = *(float4*)(eS + (h * 32 + nn) * 32 + q4 * 8);
            *(float4*)(eG + ((long)(b * PH + h) << 20) + ((long)(n0 + nn) << 10) + mt * 32 + q4 * 8) = v;
        }
    }
    #pragma unroll
    for (int g = 0; g < 12; g++)
        #pragma unroll
        for (int q = 0; q < 2; q++) {
            ps[g][q] += __shfl_xor_sync(0xFFFFFFFFu, ps[g][q], 1);
            ps[g][q] += __shfl_xor_sync(0xFFFFFFFFu, ps[g][q], 2);
        }
    __syncthreads();
    if (c4 == 0) {
        #pragma unroll
        for (int g = 0; g < 12; g++) {
            atomicAdd(&rs[g][wN * 16 + r8],     ps[g][0]);
            atomicAdd(&rs[g][wN * 16 + r8 + 8], ps[g][1]);
        }
    }
    __syncthreads();
    for (int t = tid; t < 384; t += 256) {
        int h = t >> 5, nn = t & 31;
        rsG[((long)(b * PH + h) << 10) + n0 + nn] = rs[h][nn];
    }
}

// ---------------- Stage 2 v3: head-split (6 heads/CTA), 2 CTAs/SM ----------------
// grid (32, 4, 2); z = head-group. smem: eB double (all 12 heads) + aS (6) + vS single (6)
#define S3_EB  30720                 // one e buffer: 12*32*40*2B
#define S3_AS  61440                 // aS offset (after 2 e buffers)
#define S3_V   76800                 // vS offset (aS = 6*32*40*2 = 15360)
#define S3_SM  104448                // 76800 + 6*32*72*2

__global__ void __launch_bounds__(256, 2)
mix_pv(const __half* __restrict__ eG, const __half* __restrict__ vh,
       const float* __restrict__ rsG, __half* __restrict__ oh,
       const float* __restrict__ W_w, const float* __restrict__ b_w,
       const float* __restrict__ lamb)
{
    extern __shared__ char dyn[];
    __half* eB[2] = { (__half*)dyn, (__half*)(dyn + S3_EB) };
    __half* aS = (__half*)(dyn + S3_AS);
    __half* vS = (__half*)(dyn + S3_V);
    __shared__ float wp[72], cg[6], invS[12][32];

    const int tid = threadIdx.x, w = tid >> 5, lane = tid & 31;
    const int c4 = lane & 3, r8 = lane >> 2;
    const int n0 = blockIdx.x * 32, b = blockIdx.y;
    const int hb = blockIdx.z * 6;            // head-group base

    if (tid < 72) {
        int gg = tid / 12, hh = tid % 12;
        wp[tid] = W_w[(hb + gg) * 12 + hh] * (1.0f + lamb[hb + gg]);
    }
    if (tid < 6) {
        const float ad = 1.0f / 1024.0f;
        cg[tid] = ad + (b_w[hb + tid] - ad) * (1.0f + lamb[hb + tid]);
    }
    for (int t = tid; t < 384; t += 256) {
        int hh = t >> 5, nn = t & 31;
        invS[hh][nn] = 1.0f / rsG[((long)(b * PH + hh) << 10) + n0 + nn];
    }

    auto loadE = [&](int mt, __half* buf) {
        #pragma unroll
        for (int j = 0; j < 6; j++) {                 // 12*32*4 = 1536 chunks
            int c = tid + j * 256, hh = c >> 7, nn = (c >> 2) & 31, q4 = c & 3;
            cp_async16(smem_u32(buf + (hh * 32 + nn) * 40 + q4 * 8),
                       eG + ((long)(b * PH + hh) << 20) + ((long)(n0 + nn) << 10) + mt * 32 + q4 * 8);
        }
    };
    auto loadV = [&](int mt) {
        #pragma unroll
        for (int j = 0; j < 6; j++) {                 // 6*32*8 = 1536 chunks
            int c = tid + j * 256, hh = c >> 8, rr = (c >> 3) & 31, cc = (c & 7) * 8;
            cp_async16(smem_u32(vS + (hh * 32 + rr) * 72 + cc),
                       vh + (((long)(b * PH + hb + hh) << 10) + mt * 32 + rr) * PD + cc);
        }
    };

    float acc[6][2][4];
    #pragma unroll
    for (int h = 0; h < 6; h++)
        #pragma unroll
        for (int f = 0; f < 2; f++)
            #pragma unroll
            for (int r = 0; r < 4; r++) acc[h][f][r] = 0.0f;

    loadE(0, eB[0]); loadV(0); cp_commit();           // group: E0+V0

    for (int mt = 0; mt < 32; mt++) {
        __half* ec = eB[mt & 1];
        if (mt + 1 < 32) { loadE(mt + 1, eB[(mt + 1) & 1]); cp_commit(); cp_wait<1>(); }
        else             { cp_wait<0>(); }
        __syncthreads();   // E(mt)+V(mt) ready

        // mix: 512 half2 pairs over 256 threads
        #pragma unroll
        for (int p2 = 0; p2 < 2; p2++) {
            const int p = tid + p2 * 256;
            const int nn = p >> 4, m2 = (p & 15) * 2;
            float2 f[12];
            #pragma unroll
            for (int hh = 0; hh < 12; hh++) {
                float2 e2 = __half22float2(*(const __half2*)(ec + (hh * 32 + nn) * 40 + m2));
                const float iv = invS[hh][nn];
                f[hh] = make_float2(e2.x * iv, e2.y * iv);
            }
            #pragma unroll
            for (int gg = 0; gg < 6; gg++) {
                float a0 = cg[gg], a1 = cg[gg];
                #pragma unroll
                for (int hh = 0; hh < 12; hh++) {
                    const float ww = wp[gg * 12 + hh];
                    a0 = fmaf(ww, f[hh].x, a0);
                    a1 = fmaf(ww, f[hh].y, a1);
                }
                *(__half2*)(aS + (gg * 32 + nn) * 40 + m2) = __floats2half2_rn(a0, a1);
            }
        }
        __syncthreads();   // aS ready

        // PV: 6 heads, warp w owns d-slice w*8
        #pragma unroll
        for (int h = 0; h < 6; h++) {
            #pragma unroll
            for (int kc = 0; kc < 2; kc++) {
                uint32_t b0, b1;
                ldmx2t(b0, b1, smem_u32(vS + (h * 32 + kc * 16 + (lane & 15)) * 72 + w * 8));
                #pragma unroll
                for (int f = 0; f < 2; f++) {
                    uint32_t a0, a1, a2, a3;
                    ldmx4(a0, a1, a2, a3,
                          smem_u32(aS + (h * 32 + f * 16 + (lane & 15)) * 40 + kc * 16 + ((lane >> 4) << 3)));
                    mma_f16(acc[h][f][0], acc[h][f][1], acc[h][f][2], acc[h][f][3],
                            a0, a1, a2, a3, b0, b1);
                }
            }
        }
        __syncthreads();   // PV reads of vS/aS done

        if (mt + 1 < 32) { loadV(mt + 1); cp_commit(); }   // safe: vS free now
    }

    #pragma unroll
    for (int h = 0; h < 6; h++)
        #pragma unroll
        for (int f = 0; f < 2; f++) {
            const long base = ((long)((b << 10) + n0 + f * 16 + r8)) * PC + (hb + h) * 64 + w * 8 + c4 * 2;
            *(__half2*)(oh + base)           = __floats2half2_rn(acc[h][f][0], acc[h][f][1]);
            *(__half2*)(oh + base + 8L * PC) = __floats2half2_rn(acc[h][f][2], acc[h][f][3]);
        }
}

// ---------------- launcher ----------------
extern "C" void kernel_launch(void* const* d_in, const int* in_sizes, int n_in,
                              void* d_out, int out_size)
{
    const float* x      = (const float*)d_in[0];
    const float* W_qkv  = (const float*)d_in[1];
    const float* W_proj = (const float*)d_in[2];
    const float* b_proj = (const float*)d_in[3];
    const float* W_l    = (const float*)d_in[4];
    const float* b_l    = (const float*)d_in[5];
    const float* W_w    = (const float*)d_in[6];
    const float* b_w    = (const float*)d_in[7];
    const float* lamb   = (const float*)d_in[8];
    float* out = (float*)d_out;

    __half *xh, *wqh, *wph, *qh, *kh, *vh, *e, *oh;
    float *rs;
    cudaGetSymbolAddress((void**)&xh,  g_xh);
    cudaGetSymbolAddress((void**)&wqh, g_wqh);
    cudaGetSymbolAddress((void**)&wph, g_wph);
    cudaGetSymbolAddress((void**)&qh,  g_qh);
    cudaGetSymbolAddress((void**)&kh,  g_kh);
    cudaGetSymbolAddress((void**)&vh,  g_vh);
    cudaGetSymbolAddress((void**)&e,   g_e);
    cudaGetSymbolAddress((void**)&rs,  g_rs);
    cudaGetSymbolAddress((void**)&oh,  g_oh);

    const int M = PB * PN;
    constexpr int SM_G = 3 * 2 * 128 * 72 * 2;   // 110592 (BK=64, 3 stages)

    {   const int total = N4_X + N4_WQ + N4_WP;
        f2h_all<<<(total + 255) / 256, 256>>>(x, W_qkv, W_proj, xh, wqh, wph);
    }
    {   auto kfn = gemm_h<128, 128, 64, 3, 2>;
        cudaFuncSetAttribute(kfn, cudaFuncAttributeMaxDynamicSharedMemorySize, SM_G);
        dim3 grid(3 * PC / 128, M / 128, 1);
        kfn<<<grid, 256, SM_G>>>(xh, wqh, nullptr, nullptr, M, 3 * PC, PC, 0, qh, kh, vh);
    }
    {   cudaFuncSetAttribute(qk_exp, cudaFuncAttributeMaxDynamicSharedMemorySize, S1_SM);
        dim3 grid(PN / 32, PB, 1);
        qk_exp<<<grid, 256, S1_SM>>>(qh, kh, e, rs, W_l, b_l);
    }
    {   cudaFuncSetAttribute(mix_pv, cudaFuncAttributeMaxDynamicSharedMemorySize, S3_SM);
        dim3 grid(PN / 32, PB, 2);
        mix_pv<<<grid, 256, S3_SM>>>(e, vh, rs, oh, W_w, b_w, lamb);
    }
    {   auto kfn = gemm_h<128, 128, 64, 3, 0>;
        cudaFuncSetAttribute(kfn, cudaFuncAttributeMaxDynamicSharedMemorySize, SM_G);
        dim3 grid(PC / 128, M / 128, 1);
        kfn<<<grid, 256, SM_G>>>(oh, wph, out, b_proj, M, PC, PC, PC, nullptr, nullptr, nullptr);
    }
}

// round 14
// speedup vs baseline: 1.3902x; 1.1113x over previous
#include <cuda_runtime.h>
#include <cuda_fp16.h>
#include <math.h>
#include <stdint.h>

#define PB 4
#define PN 1024
#define PC 768
#define PH 12
#define PD 64
#define PSCALE 0.125f

// ---------------- scratch ----------------
__device__ __half g_xh[(long)PB * PN * PC];
__device__ __half g_wqh[(long)3 * PC * PC];
__device__ __half g_wph[(long)PC * PC];
__device__ __half g_qh[(long)PB * PH * PN * PD];
__device__ __half g_kh[(long)PB * PH * PN * PD];
__device__ __half g_vh[(long)PB * PH * PN * PD];
__device__ __half g_e [(long)PB * PH * PN * PN];   // 100 MB unnormalized exp scores
__device__ float  g_rs[(long)PB * PH * PN];        // row sums
__device__ __half g_oh[(long)PB * PN * PC];

__device__ __forceinline__ uint32_t smem_u32(const void* p) {
    return (uint32_t)__cvta_generic_to_shared(p);
}
__device__ __forceinline__ void cp_async16(uint32_t dst, const void* src) {
    asm volatile("cp.async.cg.shared.global [%0], [%1], 16;" :: "r"(dst), "l"(src));
}
__device__ __forceinline__ void cp_commit() { asm volatile("cp.async.commit_group;"); }
template<int N_> __device__ __forceinline__ void cp_wait() {
    asm volatile("cp.async.wait_group %0;" :: "n"(N_));
}
__device__ __forceinline__ void ldmx4(uint32_t& r0, uint32_t& r1, uint32_t& r2, uint32_t& r3, uint32_t a) {
    asm volatile("ldmatrix.sync.aligned.m8n8.x4.shared.b16 {%0,%1,%2,%3}, [%4];"
                 : "=r"(r0), "=r"(r1), "=r"(r2), "=r"(r3) : "r"(a));
}
__device__ __forceinline__ void ldmx2(uint32_t& r0, uint32_t& r1, uint32_t a) {
    asm volatile("ldmatrix.sync.aligned.m8n8.x2.shared.b16 {%0,%1}, [%2];"
                 : "=r"(r0), "=r"(r1) : "r"(a));
}
__device__ __forceinline__ void ldmx2t(uint32_t& r0, uint32_t& r1, uint32_t a) {
    asm volatile("ldmatrix.sync.aligned.m8n8.x2.trans.shared.b16 {%0,%1}, [%2];"
                 : "=r"(r0), "=r"(r1) : "r"(a));
}
__device__ __forceinline__ void mma_f16(float& c0, float& c1, float& c2, float& c3,
                                        uint32_t a0, uint32_t a1, uint32_t a2, uint32_t a3,
                                        uint32_t b0, uint32_t b1) {
    asm volatile(
        "mma.sync.aligned.m16n8k16.row.col.f32.f16.f16.f32 "
        "{%0,%1,%2,%3}, {%4,%5,%6,%7}, {%8,%9}, {%0,%1,%2,%3};"
        : "+f"(c0), "+f"(c1), "+f"(c2), "+f"(c3)
        : "r"(a0), "r"(a1), "r"(a2), "r"(a3), "r"(b0), "r"(b1));
}
__device__ __forceinline__ float fexp(float x) {   // FMA-pipe exp
    float y = fmaxf(x * 1.4426950408889634f, -80.0f);
    float t = y + 12582912.0f;
    int   n = __float_as_int(t) - 0x4B400000;
    float r = y - (t - 12582912.0f);
    float p = 1.3333558e-3f;
    p = fmaf(p, r, 9.6181291e-3f);
    p = fmaf(p, r, 5.5504109e-2f);
    p = fmaf(p, r, 2.4022651e-1f);
    p = fmaf(p, r, 6.9314718e-1f);
    p = fmaf(p, r, 1.0f);
    return __int_as_float(__float_as_int(p) + (n << 23));
}

// ---------------- fused fp32 -> fp16 converts ----------------
#define N4_X  (PB * PN * PC / 4)
#define N4_WQ (3 * PC * PC / 4)
#define N4_WP (PC * PC / 4)

__global__ void __launch_bounds__(256)
f2h_all(const float* __restrict__ x, const float* __restrict__ wq,
        const float* __restrict__ wp,
        __half* __restrict__ xh, __half* __restrict__ wqh, __half* __restrict__ wph)
{
    int i = blockIdx.x * blockDim.x + threadIdx.x;
    const float* s; __half* d; int j;
    if (i < N4_X)                 { s = x;  d = xh;  j = i; }
    else if (i < N4_X + N4_WQ)    { s = wq; d = wqh; j = i - N4_X; }
    else if (i < N4_X + N4_WQ + N4_WP) { s = wp; d = wph; j = i - N4_X - N4_WQ; }
    else return;
    float4 v = ((const float4*)s)[j];
    ((__half2*)d)[j * 2]     = __floats2half2_rn(v.x, v.y);
    ((__half2*)d)[j * 2 + 1] = __floats2half2_rn(v.z, v.w);
}

// ---------------- fp16 cp.async GEMM, B^T layout (QKV + proj) ----------------
template<int BM, int BN, int BK, int STAGES, int OUTM>
__global__ void __launch_bounds__(256)
gemm_h(const __half* __restrict__ A, const __half* __restrict__ B,
       void* __restrict__ Cb, const float* __restrict__ bias,
       int M, int N, int K, int ldc,
       __half* __restrict__ qp, __half* __restrict__ kp, __half* __restrict__ vp)
{
    constexpr int BKP = BK + 8;
    constexpr int WM = 4, WN = 2;
    constexpr int WTM = BM / WM, WTN = BN / WN;
    constexpr int MT = WTM / 16, NTt = WTN / 8;
    constexpr int ASTG = BM * BKP, BSTG = BN * BKP;
    constexpr int TPR = BK / 8, RPP = 256 / TPR;
    constexpr int APASS = BM / RPP, BPASS = BN / RPP;

    extern __shared__ __half sm[];
    __half* Asm = sm;
    __half* Bsm = sm + (long)STAGES * ASTG;

    const int tid = threadIdx.x, warp = tid >> 5, lane = tid & 31;
    const int g = lane >> 2, c4 = lane & 3;
    const int wm = warp % WM, wn = warp / WM;
    const int m0 = blockIdx.y * BM, n0 = blockIdx.x * BN;

    float acc[MT][NTt][4];
    #pragma unroll
    for (int i = 0; i < MT; i++)
        #pragma unroll
        for (int j = 0; j < NTt; j++)
            #pragma unroll
            for (int r = 0; r < 4; r++) acc[i][j][r] = 0.0f;

    const int nk = K / BK;
    auto load_stage = [&](int st, int k0) {
        const int r = tid / TPR, kc = (tid % TPR) * 8;
        #pragma unroll
        for (int p = 0; p < APASS; p++)
            cp_async16(smem_u32(Asm + (long)st * ASTG + (r + p * RPP) * BKP + kc),
                       A + (long)(m0 + r + p * RPP) * K + k0 + kc);
        #pragma unroll
        for (int p = 0; p < BPASS; p++)
            cp_async16(smem_u32(Bsm + (long)st * BSTG + (r + p * RPP) * BKP + kc),
                       B + (long)(n0 + r + p * RPP) * K + k0 + kc);
    };
    auto compute_stage = [&](int st) {
        const __half* As = Asm + (long)st * ASTG;
        const __half* Bs = Bsm + (long)st * BSTG;
        #pragma unroll
        for (int kk = 0; kk < BK; kk += 16) {
            uint32_t afr[MT][4];
            #pragma unroll
            for (int mt = 0; mt < MT; mt++)
                ldmx4(afr[mt][0], afr[mt][1], afr[mt][2], afr[mt][3],
                      smem_u32(As + (wm * WTM + mt * 16 + (lane & 15)) * BKP + kk + ((lane >> 4) << 3)));
            uint32_t bfr[NTt][2];
            #pragma unroll
            for (int nt = 0; nt < NTt; nt++)
                ldmx2(bfr[nt][0], bfr[nt][1],
                      smem_u32(Bs + (wn * WTN + nt * 8 + (lane & 7)) * BKP + kk + (((lane >> 3) & 1) << 3)));
            #pragma unroll
            for (int mt = 0; mt < MT; mt++)
                #pragma unroll
                for (int nt = 0; nt < NTt; nt++)
                    mma_f16(acc[mt][nt][0], acc[mt][nt][1], acc[mt][nt][2], acc[mt][nt][3],
                            afr[mt][0], afr[mt][1], afr[mt][2], afr[mt][3],
                            bfr[nt][0], bfr[nt][1]);
        }
    };

    #pragma unroll
    for (int s = 0; s < STAGES - 1; s++) {
        if (s < nk) load_stage(s, s * BK);
        cp_commit();
    }
    for (int i = 0; i < nk; i++) {
        cp_wait<STAGES - 2>();
        __syncthreads();
        compute_stage(i % STAGES);
        const int nx = i + STAGES - 1;
        if (nx < nk) load_stage(nx % STAGES, nx * BK);
        cp_commit();
        __syncthreads();
    }

    if constexpr (OUTM == 0) {
        float* C = (float*)Cb;
        #pragma unroll
        for (int mt = 0; mt < MT; mt++) {
            const int row = m0 + wm * WTM + mt * 16 + g;
            #pragma unroll
            for (int nt = 0; nt < NTt; nt++) {
                const int col = n0 + wn * WTN + nt * 8 + c4 * 2;
                float b0 = 0.0f, b1 = 0.0f;
                if (bias) { b0 = bias[col]; b1 = bias[col + 1]; }
                *(float2*)(C + (long)row * ldc + col) =
                    make_float2(acc[mt][nt][0] + b0, acc[mt][nt][1] + b1);
                *(float2*)(C + (long)(row + 8) * ldc + col) =
                    make_float2(acc[mt][nt][2] + b0, acc[mt][nt][3] + b1);
            }
        }
    } else {
        #pragma unroll
        for (int mt = 0; mt < MT; mt++) {
            const int row = m0 + wm * WTM + mt * 16 + g;
            const int b = row >> 10, n = row & 1023;
            #pragma unroll
            for (int nt = 0; nt < NTt; nt++) {
                const int col = n0 + wn * WTN + nt * 8 + c4 * 2;
                const int s = col / PC, r2 = col % PC;
                const int h = r2 >> 6, d = r2 & 63;
                __half* dstb = (s == 0) ? qp : (s == 1) ? kp : vp;
                const float sc = (s == 0) ? PSCALE : 1.0f;
                const long base = (((long)(b * PH + h) << 10) + n) * PD + d;
                *(__half2*)(dstb + base) = __floats2half2_rn(acc[mt][nt][0] * sc, acc[mt][nt][1] * sc);
                *(__half2*)(dstb + base + 8L * PD) = __floats2half2_rn(acc[mt][nt][2] * sc, acc[mt][nt][3] * sc);
            }
        }
    }
}

// ---------------- Stage 1: QK + pre-mix + exp + row sums (unchanged) ----------------
#define S1_K0 55296
#define S1_E  165888
#define S1_SM 190464

__global__ void __launch_bounds__(256)
qk_exp(const __half* __restrict__ qh, const __half* __restrict__ kh,
       __half* __restrict__ eG, float* __restrict__ rsG,
       const float* __restrict__ W_l, const float* __restrict__ b_l)
{
    extern __shared__ char dyn[];
    __half* qT = (__half*)dyn;
    __half* kB[2] = { (__half*)(dyn + S1_K0), (__half*)(dyn + 2 * S1_K0) };
    __half* eS = (__half*)(dyn + S1_E);
    __shared__ float wl[144], bls[12];
    __shared__ float rs[12][32];

    const int tid = threadIdx.x, warp = tid >> 5, lane = tid & 31;
    const int c4 = lane & 3, r8 = lane >> 2;
    const int wA = warp & 3, wN = warp >> 2;
    const int n0 = blockIdx.x * 32, b = blockIdx.y;

    if (tid < 144) wl[tid] = W_l[tid];
    if (tid < 12)  bls[tid] = b_l[tid];
    for (int t = tid; t < 384; t += 256) ((float*)rs)[t] = 0.0f;

    #pragma unroll
    for (int it = 0; it < 12; it++) {
        int c = it * 256 + tid, h = c >> 8, rr = (c >> 3) & 31, cc = (c & 7) * 8;
        cp_async16(smem_u32(qT + (h * 32 + rr) * 72 + cc),
                   qh + (((long)(b * PH + h) << 10) + n0 + rr) * PD + cc);
    }
    cp_commit();

    auto loadk = [&](int mt, __half* buf) {
        #pragma unroll
        for (int it = 0; it < 12; it++) {
            int c = it * 256 + tid, h = c >> 8, rr = (c >> 3) & 31, cc = (c & 7) * 8;
            cp_async16(smem_u32(buf + (h * 32 + rr) * 72 + cc),
                       kh + (((long)(b * PH + h) << 10) + mt * 32 + rr) * PD + cc);
        }
    };
    loadk(0, kB[0]); cp_commit();

    float ps[12][2];
    #pragma unroll
    for (int g = 0; g < 12; g++) { ps[g][0] = 0.0f; ps[g][1] = 0.0f; }

    for (int mt = 0; mt < 32; mt++) {
        __half* cur = kB[mt & 1];
        if (mt + 1 < 32) { loadk(mt + 1, kB[(mt + 1) & 1]); cp_commit(); cp_wait<1>(); }
        else             { cp_wait<0>(); }
        __syncthreads();

        float acc[12][4];
        #pragma unroll
        for (int h = 0; h < 12; h++)
            #pragma unroll
            for (int r = 0; r < 4; r++) acc[h][r] = 0.0f;
        #pragma unroll
        for (int h = 0; h < 12; h++) {
            #pragma unroll
            for (int kc = 0; kc < 4; kc++) {
                uint32_t a0, a1, a2, a3, b0, b1;
                ldmx4(a0, a1, a2, a3,
                      smem_u32(qT + (h * 32 + wN * 16 + (lane & 15)) * 72 + kc * 16 + ((lane >> 4) << 3)));
                ldmx2(b0, b1,
                      smem_u32(cur + (h * 32 + wA * 8 + (lane & 7)) * 72 + kc * 16 + (((lane >> 3) & 1) << 3)));
                mma_f16(acc[h][0], acc[h][1], acc[h][2], acc[h][3], a0, a1, a2, a3, b0, b1);
            }
        }
        #pragma unroll
        for (int g = 0; g < 12; g++) {
            float t0 = bls[g], t1 = t0, t2 = t0, t3 = t0;
            #pragma unroll
            for (int h = 0; h < 12; h++) {
                const float w = wl[g * 12 + h];
                t0 = fmaf(w, acc[h][0], t0); t1 = fmaf(w, acc[h][1], t1);
                t2 = fmaf(w, acc[h][2], t2); t3 = fmaf(w, acc[h][3], t3);
            }
            const float e0 = fexp(t0), e1 = fexp(t1), e2 = fexp(t2), e3 = fexp(t3);
            ps[g][0] += e0 + e1; ps[g][1] += e2 + e3;
            const int mcol = wA * 8 + c4 * 2;
            *(__half2*)(eS + (g * 32 + wN * 16 + r8) * 32 + mcol)     = __floats2half2_rn(e0, e1);
            *(__half2*)(eS + (g * 32 + wN * 16 + r8 + 8) * 32 + mcol) = __floats2half2_rn(e2, e3);
        }
        __syncthreads();
        #pragma unroll
        for (int j = 0; j < 6; j++) {
            int c = tid + j * 256, h = c >> 7, nn = (c >> 2) & 31, q4 = c & 3;
            float4 v = *(float4*)(eS + (h * 32 + nn) * 32 + q4 * 8);
            *(float4*)(eG + ((long)(b * PH + h) << 20) + ((long)(n0 + nn) << 10) + mt * 32 + q4 * 8) = v;
        }
    }
    #pragma unroll
    for (int g = 0; g < 12; g++)
        #pragma unroll
        for (int q = 0; q < 2; q++) {
            ps[g][q] += __shfl_xor_sync(0xFFFFFFFFu, ps[g][q], 1);
            ps[g][q] += __shfl_xor_sync(0xFFFFFFFFu, ps[g][q], 2);
        }
    __syncthreads();
    if (c4 == 0) {
        #pragma unroll
        for (int g = 0; g < 12; g++) {
            atomicAdd(&rs[g][wN * 16 + r8],     ps[g][0]);
            atomicAdd(&rs[g][wN * 16 + r8 + 8], ps[g][1]);
        }
    }
    __syncthreads();
    for (int t = tid; t < 384; t += 256) {
        int h = t >> 5, nn = t & 31;
        rsG[((long)(b * PH + h) << 10) + n0 + nn] = rs[h][nn];
    }
}

// ---------------- Stage 2 v4: tensor-core head mix + PV ----------------
// 256 threads. smem: eB double [16h][32nn][40m] (rows 12-15 pad: h12=1.0 bias channel),
// aS [12g][32nn][40m] +16B/g skew, vS single [12][32][72], W2 [32nn][16g][24h].
#define S4_EB1 40960
#define S4_AS  81920
#define S4_V   114688
#define S4_W2  169984
#define S4_SM  194560

__global__ void __launch_bounds__(256)
mix_pv(const __half* __restrict__ eG, const __half* __restrict__ vh,
       const float* __restrict__ rsG, __half* __restrict__ oh,
       const float* __restrict__ W_w, const float* __restrict__ b_w,
       const float* __restrict__ lamb)
{
    extern __shared__ char dyn[];
    __half* eB[2] = { (__half*)dyn, (__half*)(dyn + S4_EB1) };
    __half* aS = (__half*)(dyn + S4_AS);
    __half* vS = (__half*)(dyn + S4_V);
    __half* W2 = (__half*)(dyn + S4_W2);
    __shared__ float wp[144], cg[12], invS[12][32];

    const int tid = threadIdx.x, w = tid >> 5, lane = tid & 31;
    const int c4 = lane & 3, r8 = lane >> 2;
    const int n0 = blockIdx.x * 32, b = blockIdx.y;

    if (tid < 144) wp[tid] = W_w[tid] * (1.0f + lamb[tid / 12]);
    if (tid < 12) { const float ad = 1.0f / 1024.0f; cg[tid] = ad + (b_w[tid] - ad) * (1.0f + lamb[tid]); }
    for (int t = tid; t < 384; t += 256) {
        int hh = t >> 5, nn = t & 31;
        invS[hh][nn] = 1.0f / rsG[((long)(b * PH + hh) << 10) + n0 + nn];
    }
    __syncthreads();

    // W2[nn][g][h]: h<12 -> wp*invS; h==12 -> cg (bias channel); else 0. g>=12 rows zero.
    for (int t = tid; t < 8192; t += 256) {
        int nn = t >> 8, g = (t >> 4) & 15, h = t & 15;
        float v = 0.0f;
        if (g < 12) { if (h < 12) v = wp[g * 12 + h] * invS[h][nn]; else if (h == 12) v = cg[g]; }
        W2[nn * 384 + g * 24 + h] = __float2half_rn(v);
    }
    // eB pad rows h=12..15 (both buffers): h12 = 1.0 (bias), rest 0
    for (int t = tid; t < 10240; t += 256) {
        int buf = t >= 5120, u = t % 5120;
        int h = 12 + u / 1280, rem = u % 1280, nn = rem / 40, m = rem % 40;
        eB[buf][(h * 32 + nn) * 40 + m] = __float2half_rn(h == 12 ? 1.0f : 0.0f);
    }

    auto loadE = [&](int mt, __half* buf) {
        #pragma unroll
        for (int j = 0; j < 6; j++) {                 // 12*32*4 = 1536 chunks
            int c = tid + j * 256, hh = c >> 7, nn = (c >> 2) & 31, q4 = c & 3;
            cp_async16(smem_u32(buf + (hh * 32 + nn) * 40 + q4 * 8),
                       eG + ((long)(b * PH + hh) << 20) + ((long)(n0 + nn) << 10) + mt * 32 + q4 * 8);
        }
    };
    auto loadV = [&](int mt) {
        #pragma unroll
        for (int j = 0; j < 12; j++) {                // 12*32*8 = 3072 chunks
            int c = tid + j * 256, hh = c >> 8, rr = (c >> 3) & 31, cc = (c & 7) * 8;
            cp_async16(smem_u32(vS + (hh * 32 + rr) * 72 + cc),
                       vh + (((long)(b * PH + hh) << 10) + mt * 32 + rr) * PD + cc);
        }
    };

    float acc[12][2][4];
    #pragma unroll
    for (int h = 0; h < 12; h++)
        #pragma unroll
        for (int f = 0; f < 2; f++)
            #pragma unroll
            for (int r = 0; r < 4; r++) acc[h][f][r] = 0.0f;

    loadE(0, eB[0]); loadV(0); cp_commit();

    for (int mt = 0; mt < 32; mt++) {
        __half* ec = eB[mt & 1];
        if (mt + 1 < 32) { loadE(mt + 1, eB[(mt + 1) & 1]); cp_commit(); cp_wait<1>(); }
        else             { cp_wait<0>(); }
        __syncthreads();   // E(mt)+V(mt) ready; W2/pads ready (first iter)

        // ---- MIX via tensor cores: per nn, D[16g][32m] = W2[nn] x E[16h][32m] ----
        #pragma unroll
        for (int j = 0; j < 4; j++) {
            const int nn = w + 8 * j;
            uint32_t A0, A1, A2, A3;
            ldmx4(A0, A1, A2, A3,
                  smem_u32(W2 + nn * 384 + (lane & 15) * 24 + ((lane >> 4) << 3)));
            #pragma unroll
            for (int ms = 0; ms < 4; ms++) {
                uint32_t B0, B1;
                ldmx2t(B0, B1, smem_u32(ec + ((lane & 15) * 32 + nn) * 40 + ms * 8));
                float d0 = 0.0f, d1 = 0.0f, d2 = 0.0f, d3 = 0.0f;
                mma_f16(d0, d1, d2, d3, A0, A1, A2, A3, B0, B1);
                const int m = ms * 8 + c4 * 2;
                *(__half2*)(aS + (r8 * 32 + nn) * 40 + r8 * 8 + m) = __floats2half2_rn(d0, d1);
                if (r8 < 4)
                    *(__half2*)(aS + ((r8 + 8) * 32 + nn) * 40 + (r8 + 8) * 8 + m) = __floats2half2_rn(d2, d3);
            }
        }
        __syncthreads();   // aS ready

        // ---- PV: warp w owns d-slice w*8 (R11-proven, skewed aS) ----
        #pragma unroll
        for (int h = 0; h < 12; h++) {
            #pragma unroll
            for (int kc = 0; kc < 2; kc++) {
                uint32_t b0, b1;
                ldmx2t(b0, b1, smem_u32(vS + (h * 32 + kc * 16 + (lane & 15)) * 72 + w * 8));
                #pragma unroll
                for (int f = 0; f < 2; f++) {
                    uint32_t a0, a1, a2, a3;
                    ldmx4(a0, a1, a2, a3,
                          smem_u32(aS + (h * 32 + f * 16 + (lane & 15)) * 40 + h * 8 + kc * 16 + ((lane >> 4) << 3)));
                    mma_f16(acc[h][f][0], acc[h][f][1], acc[h][f][2], acc[h][f][3],
                            a0, a1, a2, a3, b0, b1);
                }
            }
        }
        __syncthreads();   // PV reads done

        if (mt + 1 < 32) { loadV(mt + 1); cp_commit(); }
    }

    #pragma unroll
    for (int h = 0; h < 12; h++)
        #pragma unroll
        for (int f = 0; f < 2; f++) {
            const long base = ((long)((b << 10) + n0 + f * 16 + r8)) * PC + h * 64 + w * 8 + c4 * 2;
            *(__half2*)(oh + base)           = __floats2half2_rn(acc[h][f][0], acc[h][f][1]);
            *(__half2*)(oh + base + 8L * PC) = __floats2half2_rn(acc[h][f][2], acc[h][f][3]);
        }
}

// ---------------- launcher ----------------
extern "C" void kernel_launch(void* const* d_in, const int* in_sizes, int n_in,
                              void* d_out, int out_size)
{
    const float* x      = (const float*)d_in[0];
    const float* W_qkv  = (const float*)d_in[1];
    const float* W_proj = (const float*)d_in[2];
    const float* b_proj = (const float*)d_in[3];
    const float* W_l    = (const float*)d_in[4];
    const float* b_l    = (const float*)d_in[5];
    const float* W_w    = (const float*)d_in[6];
    const float* b_w    = (const float*)d_in[7];
    const float* lamb   = (const float*)d_in[8];
    float* out = (float*)d_out;

    __half *xh, *wqh, *wph, *qh, *kh, *vh, *e, *oh;
    float *rs;
    cudaGetSymbolAddress((void**)&xh,  g_xh);
    cudaGetSymbolAddress((void**)&wqh, g_wqh);
    cudaGetSymbolAddress((void**)&wph, g_wph);
    cudaGetSymbolAddress((void**)&qh,  g_qh);
    cudaGetSymbolAddress((void**)&kh,  g_kh);
    cudaGetSymbolAddress((void**)&vh,  g_vh);
    cudaGetSymbolAddress((void**)&e,   g_e);
    cudaGetSymbolAddress((void**)&rs,  g_rs);
    cudaGetSymbolAddress((void**)&oh,  g_oh);

    const int M = PB * PN;
    constexpr int SM_G = 3 * 2 * 128 * 72 * 2;   // 110592 (BK=64, 3 stages)

    {   const int total = N4_X + N4_WQ + N4_WP;
        f2h_all<<<(total + 255) / 256, 256>>>(x, W_qkv, W_proj, xh, wqh, wph);
    }
    {   auto kfn = gemm_h<128, 128, 64, 3, 2>;
        cudaFuncSetAttribute(kfn, cudaFuncAttributeMaxDynamicSharedMemorySize, SM_G);
        dim3 grid(3 * PC / 128, M / 128, 1);
        kfn<<<grid, 256, SM_G>>>(xh, wqh, nullptr, nullptr, M, 3 * PC, PC, 0, qh, kh, vh);
    }
    {   cudaFuncSetAttribute(qk_exp, cudaFuncAttributeMaxDynamicSharedMemorySize, S1_SM);
        dim3 grid(PN / 32, PB, 1);
        qk_exp<<<grid, 256, S1_SM>>>(qh, kh, e, rs, W_l, b_l);
    }
    {   cudaFuncSetAttribute(mix_pv, cudaFuncAttributeMaxDynamicSharedMemorySize, S4_SM);
        dim3 grid(PN / 32, PB, 1);
        mix_pv<<<grid, 256, S4_SM>>>(e, vh, rs, oh, W_w, b_w, lamb);
    }
    {   auto kfn = gemm_h<128, 128, 64, 3, 0>;
        cudaFuncSetAttribute(kfn, cudaFuncAttributeMaxDynamicSharedMemorySize, SM_G);
        dim3 grid(PC / 128, M / 128, 1);
        kfn<<<grid, 256, SM_G>>>(oh, wph, out, b_proj, M, PC, PC, PC, nullptr, nullptr, nullptr);
    }
}

// round 15
// speedup vs baseline: 1.3907x; 1.0003x over previous
#include <cuda_runtime.h>
#include <cuda_fp16.h>
#include <math.h>
#include <stdint.h>

#define PB 4
#define PN 1024
#define PC 768
#define PH 12
#define PD 64
#define PSCALE 0.125f

// ---------------- scratch ----------------
__device__ __half g_xh[(long)PB * PN * PC];
__device__ __half g_wqh[(long)3 * PC * PC];
__device__ __half g_wph[(long)PC * PC];
__device__ __half g_qh[(long)PB * PH * PN * PD];
__device__ __half g_kh[(long)PB * PH * PN * PD];
__device__ __half g_vh[(long)PB * PH * PN * PD];
__device__ __half g_e [(long)PB * PH * PN * PN];   // 100 MB unnormalized exp scores
__device__ float  g_rs[(long)PB * PH * PN];        // row sums
__device__ __half g_oh[(long)PB * PN * PC];

__device__ __forceinline__ uint32_t smem_u32(const void* p) {
    return (uint32_t)__cvta_generic_to_shared(p);
}
__device__ __forceinline__ void cp_async16(uint32_t dst, const void* src) {
    asm volatile("cp.async.cg.shared.global [%0], [%1], 16;" :: "r"(dst), "l"(src));
}
__device__ __forceinline__ void cp_commit() { asm volatile("cp.async.commit_group;"); }
template<int N_> __device__ __forceinline__ void cp_wait() {
    asm volatile("cp.async.wait_group %0;" :: "n"(N_));
}
__device__ __forceinline__ void ldmx4(uint32_t& r0, uint32_t& r1, uint32_t& r2, uint32_t& r3, uint32_t a) {
    asm volatile("ldmatrix.sync.aligned.m8n8.x4.shared.b16 {%0,%1,%2,%3}, [%4];"
                 : "=r"(r0), "=r"(r1), "=r"(r2), "=r"(r3) : "r"(a));
}
__device__ __forceinline__ void ldmx2(uint32_t& r0, uint32_t& r1, uint32_t a) {
    asm volatile("ldmatrix.sync.aligned.m8n8.x2.shared.b16 {%0,%1}, [%2];"
                 : "=r"(r0), "=r"(r1) : "r"(a));
}
__device__ __forceinline__ void ldmx2t(uint32_t& r0, uint32_t& r1, uint32_t a) {
    asm volatile("ldmatrix.sync.aligned.m8n8.x2.trans.shared.b16 {%0,%1}, [%2];"
                 : "=r"(r0), "=r"(r1) : "r"(a));
}
__device__ __forceinline__ void mma_f16(float& c0, float& c1, float& c2, float& c3,
                                        uint32_t a0, uint32_t a1, uint32_t a2, uint32_t a3,
                                        uint32_t b0, uint32_t b1) {
    asm volatile(
        "mma.sync.aligned.m16n8k16.row.col.f32.f16.f16.f32 "
        "{%0,%1,%2,%3}, {%4,%5,%6,%7}, {%8,%9}, {%0,%1,%2,%3};"
        : "+f"(c0), "+f"(c1), "+f"(c2), "+f"(c3)
        : "r"(a0), "r"(a1), "r"(a2), "r"(a3), "r"(b0), "r"(b1));
}
__device__ __forceinline__ float fexp(float x) {   // FMA-pipe exp
    float y = fmaxf(x * 1.4426950408889634f, -80.0f);
    float t = y + 12582912.0f;
    int   n = __float_as_int(t) - 0x4B400000;
    float r = y - (t - 12582912.0f);
    float p = 1.3333558e-3f;
    p = fmaf(p, r, 9.6181291e-3f);
    p = fmaf(p, r, 5.5504109e-2f);
    p = fmaf(p, r, 2.4022651e-1f);
    p = fmaf(p, r, 6.9314718e-1f);
    p = fmaf(p, r, 1.0f);
    return __int_as_float(__float_as_int(p) + (n << 23));
}

// ---------------- fused fp32 -> fp16 converts ----------------
#define N4_X  (PB * PN * PC / 4)
#define N4_WQ (3 * PC * PC / 4)
#define N4_WP (PC * PC / 4)

__global__ void __launch_bounds__(256)
f2h_all(const float* __restrict__ x, const float* __restrict__ wq,
        const float* __restrict__ wp,
        __half* __restrict__ xh, __half* __restrict__ wqh, __half* __restrict__ wph)
{
    int i = blockIdx.x * blockDim.x + threadIdx.x;
    const float* s; __half* d; int j;
    if (i < N4_X)                 { s = x;  d = xh;  j = i; }
    else if (i < N4_X + N4_WQ)    { s = wq; d = wqh; j = i - N4_X; }
    else if (i < N4_X + N4_WQ + N4_WP) { s = wp; d = wph; j = i - N4_X - N4_WQ; }
    else return;
    float4 v = ((const float4*)s)[j];
    ((__half2*)d)[j * 2]     = __floats2half2_rn(v.x, v.y);
    ((__half2*)d)[j * 2 + 1] = __floats2half2_rn(v.z, v.w);
}

// ---------------- fp16 cp.async GEMM, B^T layout (QKV + proj) ----------------
template<int BM, int BN, int BK, int STAGES, int OUTM>
__global__ void __launch_bounds__(256)
gemm_h(const __half* __restrict__ A, const __half* __restrict__ B,
       void* __restrict__ Cb, const float* __restrict__ bias,
       int M, int N, int K, int ldc,
       __half* __restrict__ qp, __half* __restrict__ kp, __half* __restrict__ vp)
{
    constexpr int BKP = BK + 8;
    constexpr int WM = 4, WN = 2;
    constexpr int WTM = BM / WM, WTN = BN / WN;
    constexpr int MT = WTM / 16, NTt = WTN / 8;
    constexpr int ASTG = BM * BKP, BSTG = BN * BKP;
    constexpr int TPR = BK / 8, RPP = 256 / TPR;
    constexpr int APASS = BM / RPP, BPASS = BN / RPP;

    extern __shared__ __half sm[];
    __half* Asm = sm;
    __half* Bsm = sm + (long)STAGES * ASTG;

    const int tid = threadIdx.x, warp = tid >> 5, lane = tid & 31;
    const int g = lane >> 2, c4 = lane & 3;
    const int wm = warp % WM, wn = warp / WM;
    const int m0 = blockIdx.y * BM, n0 = blockIdx.x * BN;

    float acc[MT][NTt][4];
    #pragma unroll
    for (int i = 0; i < MT; i++)
        #pragma unroll
        for (int j = 0; j < NTt; j++)
            #pragma unroll
            for (int r = 0; r < 4; r++) acc[i][j][r] = 0.0f;

    const int nk = K / BK;
    auto load_stage = [&](int st, int k0) {
        const int r = tid / TPR, kc = (tid % TPR) * 8;
        #pragma unroll
        for (int p = 0; p < APASS; p++)
            cp_async16(smem_u32(Asm + (long)st * ASTG + (r + p * RPP) * BKP + kc),
                       A + (long)(m0 + r + p * RPP) * K + k0 + kc);
        #pragma unroll
        for (int p = 0; p < BPASS; p++)
            cp_async16(smem_u32(Bsm + (long)st * BSTG + (r + p * RPP) * BKP + kc),
                       B + (long)(n0 + r + p * RPP) * K + k0 + kc);
    };
    auto compute_stage = [&](int st) {
        const __half* As = Asm + (long)st * ASTG;
        const __half* Bs = Bsm + (long)st * BSTG;
        #pragma unroll
        for (int kk = 0; kk < BK; kk += 16) {
            uint32_t afr[MT][4];
            #pragma unroll
            for (int mt = 0; mt < MT; mt++)
                ldmx4(afr[mt][0], afr[mt][1], afr[mt][2], afr[mt][3],
                      smem_u32(As + (wm * WTM + mt * 16 + (lane & 15)) * BKP + kk + ((lane >> 4) << 3)));
            uint32_t bfr[NTt][2];
            #pragma unroll
            for (int nt = 0; nt < NTt; nt++)
                ldmx2(bfr[nt][0], bfr[nt][1],
                      smem_u32(Bs + (wn * WTN + nt * 8 + (lane & 7)) * BKP + kk + (((lane >> 3) & 1) << 3)));
            #pragma unroll
            for (int mt = 0; mt < MT; mt++)
                #pragma unroll
                for (int nt = 0; nt < NTt; nt++)
                    mma_f16(acc[mt][nt][0], acc[mt][nt][1], acc[mt][nt][2], acc[mt][nt][3],
                            afr[mt][0], afr[mt][1], afr[mt][2], afr[mt][3],
                            bfr[nt][0], bfr[nt][1]);
        }
    };

    #pragma unroll
    for (int s = 0; s < STAGES - 1; s++) {
        if (s < nk) load_stage(s, s * BK);
        cp_commit();
    }
    for (int i = 0; i < nk; i++) {
        cp_wait<STAGES - 2>();
        __syncthreads();
        compute_stage(i % STAGES);
        const int nx = i + STAGES - 1;
        if (nx < nk) load_stage(nx % STAGES, nx * BK);
        cp_commit();
        __syncthreads();
    }

    if constexpr (OUTM == 0) {
        float* C = (float*)Cb;
        #pragma unroll
        for (int mt = 0; mt < MT; mt++) {
            const int row = m0 + wm * WTM + mt * 16 + g;
            #pragma unroll
            for (int nt = 0; nt < NTt; nt++) {
                const int col = n0 + wn * WTN + nt * 8 + c4 * 2;
                float b0 = 0.0f, b1 = 0.0f;
                if (bias) { b0 = bias[col]; b1 = bias[col + 1]; }
                *(float2*)(C + (long)row * ldc + col) =
                    make_float2(acc[mt][nt][0] + b0, acc[mt][nt][1] + b1);
                *(float2*)(C + (long)(row + 8) * ldc + col) =
                    make_float2(acc[mt][nt][2] + b0, acc[mt][nt][3] + b1);
            }
        }
    } else {
        #pragma unroll
        for (int mt = 0; mt < MT; mt++) {
            const int row = m0 + wm * WTM + mt * 16 + g;
            const int b = row >> 10, n = row & 1023;
            #pragma unroll
            for (int nt = 0; nt < NTt; nt++) {
                const int col = n0 + wn * WTN + nt * 8 + c4 * 2;
                const int s = col / PC, r2 = col % PC;
                const int h = r2 >> 6, d = r2 & 63;
                __half* dstb = (s == 0) ? qp : (s == 1) ? kp : vp;
                const float sc = (s == 0) ? PSCALE : 1.0f;
                const long base = (((long)(b * PH + h) << 10) + n) * PD + d;
                *(__half2*)(dstb + base) = __floats2half2_rn(acc[mt][nt][0] * sc, acc[mt][nt][1] * sc);
                *(__half2*)(dstb + base + 8L * PD) = __floats2half2_rn(acc[mt][nt][2] * sc, acc[mt][nt][3] * sc);
            }
        }
    }
}

// ---------------- Stage 1: QK + pre-mix + exp + row sums (unchanged) ----------------
#define S1_K0 55296
#define S1_E  165888
#define S1_SM 190464

__global__ void __launch_bounds__(256)
qk_exp(const __half* __restrict__ qh, const __half* __restrict__ kh,
       __half* __restrict__ eG, float* __restrict__ rsG,
       const float* __restrict__ W_l, const float* __restrict__ b_l)
{
    extern __shared__ char dyn[];
    __half* qT = (__half*)dyn;
    __half* kB[2] = { (__half*)(dyn + S1_K0), (__half*)(dyn + 2 * S1_K0) };
    __half* eS = (__half*)(dyn + S1_E);
    __shared__ float wl[144], bls[12];
    __shared__ float rs[12][32];

    const int tid = threadIdx.x, warp = tid >> 5, lane = tid & 31;
    const int c4 = lane & 3, r8 = lane >> 2;
    const int wA = warp & 3, wN = warp >> 2;
    const int n0 = blockIdx.x * 32, b = blockIdx.y;

    if (tid < 144) wl[tid] = W_l[tid];
    if (tid < 12)  bls[tid] = b_l[tid];
    for (int t = tid; t < 384; t += 256) ((float*)rs)[t] = 0.0f;

    #pragma unroll
    for (int it = 0; it < 12; it++) {
        int c = it * 256 + tid, h = c >> 8, rr = (c >> 3) & 31, cc = (c & 7) * 8;
        cp_async16(smem_u32(qT + (h * 32 + rr) * 72 + cc),
                   qh + (((long)(b * PH + h) << 10) + n0 + rr) * PD + cc);
    }
    cp_commit();

    auto loadk = [&](int mt, __half* buf) {
        #pragma unroll
        for (int it = 0; it < 12; it++) {
            int c = it * 256 + tid, h = c >> 8, rr = (c >> 3) & 31, cc = (c & 7) * 8;
            cp_async16(smem_u32(buf + (h * 32 + rr) * 72 + cc),
                       kh + (((long)(b * PH + h) << 10) + mt * 32 + rr) * PD + cc);
        }
    };
    loadk(0, kB[0]); cp_commit();

    float ps[12][2];
    #pragma unroll
    for (int g = 0; g < 12; g++) { ps[g][0] = 0.0f; ps[g][1] = 0.0f; }

    for (int mt = 0; mt < 32; mt++) {
        __half* cur = kB[mt & 1];
        if (mt + 1 < 32) { loadk(mt + 1, kB[(mt + 1) & 1]); cp_commit(); cp_wait<1>(); }
        else             { cp_wait<0>(); }
        __syncthreads();

        float acc[12][4];
        #pragma unroll
        for (int h = 0; h < 12; h++)
            #pragma unroll
            for (int r = 0; r < 4; r++) acc[h][r] = 0.0f;
        #pragma unroll
        for (int h = 0; h < 12; h++) {
            #pragma unroll
            for (int kc = 0; kc < 4; kc++) {
                uint32_t a0, a1, a2, a3, b0, b1;
                ldmx4(a0, a1, a2, a3,
                      smem_u32(qT + (h * 32 + wN * 16 + (lane & 15)) * 72 + kc * 16 + ((lane >> 4) << 3)));
                ldmx2(b0, b1,
                      smem_u32(cur + (h * 32 + wA * 8 + (lane & 7)) * 72 + kc * 16 + (((lane >> 3) & 1) << 3)));
                mma_f16(acc[h][0], acc[h][1], acc[h][2], acc[h][3], a0, a1, a2, a3, b0, b1);
            }
        }
        #pragma unroll
        for (int g = 0; g < 12; g++) {
            float t0 = bls[g], t1 = t0, t2 = t0, t3 = t0;
            #pragma unroll
            for (int h = 0; h < 12; h++) {
                const float w = wl[g * 12 + h];
                t0 = fmaf(w, acc[h][0], t0); t1 = fmaf(w, acc[h][1], t1);
                t2 = fmaf(w, acc[h][2], t2); t3 = fmaf(w, acc[h][3], t3);
            }
            const float e0 = fexp(t0), e1 = fexp(t1), e2 = fexp(t2), e3 = fexp(t3);
            ps[g][0] += e0 + e1; ps[g][1] += e2 + e3;
            const int mcol = wA * 8 + c4 * 2;
            *(__half2*)(eS + (g * 32 + wN * 16 + r8) * 32 + mcol)     = __floats2half2_rn(e0, e1);
            *(__half2*)(eS + (g * 32 + wN * 16 + r8 + 8) * 32 + mcol) = __floats2half2_rn(e2, e3);
        }
        __syncthreads();
        #pragma unroll
        for (int j = 0; j < 6; j++) {
            int c = tid + j * 256, h = c >> 7, nn = (c >> 2) & 31, q4 = c & 3;
            float4 v = *(float4*)(eS + (h * 32 + nn) * 32 + q4 * 8);
            *(float4*)(eG + ((long)(b * PH + h) << 20) + ((long)(n0 + nn) << 10) + mt * 32 + q4 * 8) = v;
        }
    }
    #pragma unroll
    for (int g = 0; g < 12; g++)
        #pragma unroll
        for (int q = 0; q < 2; q++) {
            ps[g][q] += __shfl_xor_sync(0xFFFFFFFFu, ps[g][q], 1);
            ps[g][q] += __shfl_xor_sync(0xFFFFFFFFu, ps[g][q], 2);
        }
    __syncthreads();
    if (c4 == 0) {
        #pragma unroll
        for (int g = 0; g < 12; g++) {
            atomicAdd(&rs[g][wN * 16 + r8],     ps[g][0]);
            atomicAdd(&rs[g][wN * 16 + r8 + 8], ps[g][1]);
        }
    }
    __syncthreads();
    for (int t = tid; t < 384; t += 256) {
        int h = t >> 5, nn = t & 31;
        rsG[((long)(b * PH + h) << 10) + n0 + nn] = rs[h][nn];
    }
}

// ---------------- Stage 2 v5: tensor-core head mix + PV, 512 threads ----------------
// smem layout identical to R14: eB double [16h][32nn][40m] (h12 = bias channel),
// aS [12g][32nn][40m] + g*16B skew, vS [12][32][72], W2 [32nn][16g][24h].
#define S4_EB1 40960
#define S4_AS  81920
#define S4_V   114688
#define S4_W2  169984
#define S4_SM  194560

__global__ void __launch_bounds__(512)
mix_pv(const __half* __restrict__ eG, const __half* __restrict__ vh,
       const float* __restrict__ rsG, __half* __restrict__ oh,
       const float* __restrict__ W_w, const float* __restrict__ b_w,
       const float* __restrict__ lamb)
{
    extern __shared__ char dyn[];
    __half* eB[2] = { (__half*)dyn, (__half*)(dyn + S4_EB1) };
    __half* aS = (__half*)(dyn + S4_AS);
    __half* vS = (__half*)(dyn + S4_V);
    __half* W2 = (__half*)(dyn + S4_W2);
    __shared__ float wp[144], cg[12], invS[12][32];

    const int tid = threadIdx.x, warp = tid >> 5, lane = tid & 31;
    const int c4 = lane & 3, r8 = lane >> 2;
    const int wg = warp >> 3, w8 = warp & 7;       // PV: head-group, d-slice
    const int n0 = blockIdx.x * 32, b = blockIdx.y;

    if (tid < 144) wp[tid] = W_w[tid] * (1.0f + lamb[tid / 12]);
    if (tid < 12) { const float ad = 1.0f / 1024.0f; cg[tid] = ad + (b_w[tid] - ad) * (1.0f + lamb[tid]); }
    if (tid < 384) {
        int hh = tid >> 5, nn = tid & 31;
        invS[hh][nn] = 1.0f / rsG[((long)(b * PH + hh) << 10) + n0 + nn];
    }
    __syncthreads();

    // W2[nn][g][h]: h<12 -> wp*invS; h==12 -> cg (bias channel); else 0. g>=12 rows zero.
    for (int t = tid; t < 8192; t += 512) {
        int nn = t >> 8, g = (t >> 4) & 15, h = t & 15;
        float v = 0.0f;
        if (g < 12) { if (h < 12) v = wp[g * 12 + h] * invS[h][nn]; else if (h == 12) v = cg[g]; }
        W2[nn * 384 + g * 24 + h] = __float2half_rn(v);
    }
    // eB pad rows h=12..15 (both buffers): h12 = 1.0 (bias), rest 0
    for (int t = tid; t < 10240; t += 512) {
        int buf = t >= 5120, u = t % 5120;
        int h = 12 + u / 1280, rem = u % 1280, nn = rem / 40, m = rem % 40;
        eB[buf][(h * 32 + nn) * 40 + m] = __float2half_rn(h == 12 ? 1.0f : 0.0f);
    }

    auto loadE = [&](int mt, __half* buf) {
        #pragma unroll
        for (int j = 0; j < 3; j++) {                 // 12*32*4 = 1536 chunks
            int c = tid + j * 512, hh = c >> 7, nn = (c >> 2) & 31, q4 = c & 3;
            cp_async16(smem_u32(buf + (hh * 32 + nn) * 40 + q4 * 8),
                       eG + ((long)(b * PH + hh) << 20) + ((long)(n0 + nn) << 10) + mt * 32 + q4 * 8);
        }
    };
    auto loadV = [&](int mt) {
        #pragma unroll
        for (int j = 0; j < 6; j++) {                 // 12*32*8 = 3072 chunks
            int c = tid + j * 512, hh = c >> 8, rr = (c >> 3) & 31, cc = (c & 7) * 8;
            cp_async16(smem_u32(vS + (hh * 32 + rr) * 72 + cc),
                       vh + (((long)(b * PH + hh) << 10) + mt * 32 + rr) * PD + cc);
        }
    };

    float acc[6][2][4];                               // 6 heads (group wg) x 2 row-halves
    #pragma unroll
    for (int h = 0; h < 6; h++)
        #pragma unroll
        for (int f = 0; f < 2; f++)
            #pragma unroll
            for (int r = 0; r < 4; r++) acc[h][f][r] = 0.0f;

    loadE(0, eB[0]); loadV(0); cp_commit();

    for (int mt = 0; mt < 32; mt++) {
        __half* ec = eB[mt & 1];
        if (mt + 1 < 32) { loadE(mt + 1, eB[(mt + 1) & 1]); cp_commit(); cp_wait<1>(); }
        else             { cp_wait<0>(); }
        __syncthreads();   // E(mt)+V(mt) ready; W2/pads ready (first iter)

        // ---- MIX via tensor cores: warp handles nn = warp, warp+16 ----
        #pragma unroll
        for (int j = 0; j < 2; j++) {
            const int nn = warp + 16 * j;
            uint32_t A0, A1, A2, A3;
            ldmx4(A0, A1, A2, A3,
                  smem_u32(W2 + nn * 384 + (lane & 15) * 24 + ((lane >> 4) << 3)));
            #pragma unroll
            for (int ms = 0; ms < 4; ms++) {
                uint32_t B0, B1;
                ldmx2t(B0, B1, smem_u32(ec + ((lane & 15) * 32 + nn) * 40 + ms * 8));
                float d0 = 0.0f, d1 = 0.0f, d2 = 0.0f, d3 = 0.0f;
                mma_f16(d0, d1, d2, d3, A0, A1, A2, A3, B0, B1);
                const int m = ms * 8 + c4 * 2;
                *(__half2*)(aS + (r8 * 32 + nn) * 40 + r8 * 8 + m) = __floats2half2_rn(d0, d1);
                if (r8 < 4)
                    *(__half2*)(aS + ((r8 + 8) * 32 + nn) * 40 + (r8 + 8) * 8 + m) = __floats2half2_rn(d2, d3);
            }
        }
        __syncthreads();   // aS ready

        // ---- PV: warp (wg, w8) -> heads wg*6..+6, d-slice w8*8 ----
        #pragma unroll
        for (int hh = 0; hh < 6; hh++) {
            const int h = wg * 6 + hh;
            #pragma unroll
            for (int kc = 0; kc < 2; kc++) {
                uint32_t b0, b1;
                ldmx2t(b0, b1, smem_u32(vS + (h * 32 + kc * 16 + (lane & 15)) * 72 + w8 * 8));
                #pragma unroll
                for (int f = 0; f < 2; f++) {
                    uint32_t a0, a1, a2, a3;
                    ldmx4(a0, a1, a2, a3,
                          smem_u32(aS + (h * 32 + f * 16 + (lane & 15)) * 40 + h * 8 + kc * 16 + ((lane >> 4) << 3)));
                    mma_f16(acc[hh][f][0], acc[hh][f][1], acc[hh][f][2], acc[hh][f][3],
                            a0, a1, a2, a3, b0, b1);
                }
            }
        }
        __syncthreads();   // PV reads done

        if (mt + 1 < 32) { loadV(mt + 1); cp_commit(); }
    }

    #pragma unroll
    for (int hh = 0; hh < 6; hh++) {
        const int h = wg * 6 + hh;
        #pragma unroll
        for (int f = 0; f < 2; f++) {
            const long base = ((long)((b << 10) + n0 + f * 16 + r8)) * PC + h * 64 + w8 * 8 + c4 * 2;
            *(__half2*)(oh + base)           = __floats2half2_rn(acc[hh][f][0], acc[hh][f][1]);
            *(__half2*)(oh + base + 8L * PC) = __floats2half2_rn(acc[hh][f][2], acc[hh][f][3]);
        }
    }
}

// ---------------- launcher ----------------
extern "C" void kernel_launch(void* const* d_in, const int* in_sizes, int n_in,
                              void* d_out, int out_size)
{
    const float* x      = (const float*)d_in[0];
    const float* W_qkv  = (const float*)d_in[1];
    const float* W_proj = (const float*)d_in[2];
    const float* b_proj = (const float*)d_in[3];
    const float* W_l    = (const float*)d_in[4];
    const float* b_l    = (const float*)d_in[5];
    const float* W_w    = (const float*)d_in[6];
    const float* b_w    = (const float*)d_in[7];
    const float* lamb   = (const float*)d_in[8];
    float* out = (float*)d_out;

    __half *xh, *wqh, *wph, *qh, *kh, *vh, *e, *oh;
    float *rs;
    cudaGetSymbolAddress((void**)&xh,  g_xh);
    cudaGetSymbolAddress((void**)&wqh, g_wqh);
    cudaGetSymbolAddress((void**)&wph, g_wph);
    cudaGetSymbolAddress((void**)&qh,  g_qh);
    cudaGetSymbolAddress((void**)&kh,  g_kh);
    cudaGetSymbolAddress((void**)&vh,  g_vh);
    cudaGetSymbolAddress((void**)&e,   g_e);
    cudaGetSymbolAddress((void**)&rs,  g_rs);
    cudaGetSymbolAddress((void**)&oh,  g_oh);

    const int M = PB * PN;
    constexpr int SM_G = 3 * 2 * 128 * 72 * 2;   // 110592 (BK=64, 3 stages)

    {   const int total = N4_X + N4_WQ + N4_WP;
        f2h_all<<<(total + 255) / 256, 256>>>(x, W_qkv, W_proj, xh, wqh, wph);
    }
    {   auto kfn = gemm_h<128, 128, 64, 3, 2>;
        cudaFuncSetAttribute(kfn, cudaFuncAttributeMaxDynamicSharedMemorySize, SM_G);
        dim3 grid(3 * PC / 128, M / 128, 1);
        kfn<<<grid, 256, SM_G>>>(xh, wqh, nullptr, nullptr, M, 3 * PC, PC, 0, qh, kh, vh);
    }
    {   cudaFuncSetAttribute(qk_exp, cudaFuncAttributeMaxDynamicSharedMemorySize, S1_SM);
        dim3 grid(PN / 32, PB, 1);
        qk_exp<<<grid, 256, S1_SM>>>(qh, kh, e, rs, W_l, b_l);
    }
    {   cudaFuncSetAttribute(mix_pv, cudaFuncAttributeMaxDynamicSharedMemorySize, S4_SM);
        dim3 grid(PN / 32, PB, 1);
        mix_pv<<<grid, 512, S4_SM>>>(e, vh, rs, oh, W_w, b_w, lamb);
    }
    {   auto kfn = gemm_h<128, 128, 64, 3, 0>;
        cudaFuncSetAttribute(kfn, cudaFuncAttributeMaxDynamicSharedMemorySize, SM_G);
        dim3 grid(PC / 128, M / 128, 1);
        kfn<<<grid, 256, SM_G>>>(oh, wph, out, b_proj, M, PC, PC, PC, nullptr, nullptr, nullptr);
    }
}

// round 16
// speedup vs baseline: 1.5191x; 1.0923x over previous
#include <cuda_runtime.h>
#include <cuda_fp16.h>
#include <math.h>
#include <stdint.h>

#define PB 4
#define PN 1024
#define PC 768
#define PH 12
#define PD 64
#define PSCALE 0.125f

// ---------------- scratch ----------------
__device__ __half g_xh[(long)PB * PN * PC];
__device__ __half g_wqh[(long)3 * PC * PC];
__device__ __half g_wph[(long)PC * PC];
__device__ __half g_qh[(long)PB * PH * PN * PD];
__device__ __half g_kh[(long)PB * PH * PN * PD];
__device__ __half g_vh[(long)PB * PH * PN * PD];
__device__ __half g_e [(long)PB * PH * PN * PN];   // 100 MB unnormalized exp scores
__device__ float  g_rs[(long)PB * PH * PN];        // row sums
__device__ __half g_oh[(long)PB * PN * PC];

__device__ __forceinline__ uint32_t smem_u32(const void* p) {
    return (uint32_t)__cvta_generic_to_shared(p);
}
__device__ __forceinline__ void cp_async16(uint32_t dst, const void* src) {
    asm volatile("cp.async.cg.shared.global [%0], [%1], 16;" :: "r"(dst), "l"(src));
}
__device__ __forceinline__ void cp_commit() { asm volatile("cp.async.commit_group;"); }
template<int N_> __device__ __forceinline__ void cp_wait() {
    asm volatile("cp.async.wait_group %0;" :: "n"(N_));
}
__device__ __forceinline__ void ldmx4(uint32_t& r0, uint32_t& r1, uint32_t& r2, uint32_t& r3, uint32_t a) {
    asm volatile("ldmatrix.sync.aligned.m8n8.x4.shared.b16 {%0,%1,%2,%3}, [%4];"
                 : "=r"(r0), "=r"(r1), "=r"(r2), "=r"(r3) : "r"(a));
}
__device__ __forceinline__ void ldmx2(uint32_t& r0, uint32_t& r1, uint32_t a) {
    asm volatile("ldmatrix.sync.aligned.m8n8.x2.shared.b16 {%0,%1}, [%2];"
                 : "=r"(r0), "=r"(r1) : "r"(a));
}
__device__ __forceinline__ void ldmx2t(uint32_t& r0, uint32_t& r1, uint32_t a) {
    asm volatile("ldmatrix.sync.aligned.m8n8.x2.trans.shared.b16 {%0,%1}, [%2];"
                 : "=r"(r0), "=r"(r1) : "r"(a));
}
__device__ __forceinline__ void mma_f16(float& c0, float& c1, float& c2, float& c3,
                                        uint32_t a0, uint32_t a1, uint32_t a2, uint32_t a3,
                                        uint32_t b0, uint32_t b1) {
    asm volatile(
        "mma.sync.aligned.m16n8k16.row.col.f32.f16.f16.f32 "
        "{%0,%1,%2,%3}, {%4,%5,%6,%7}, {%8,%9}, {%0,%1,%2,%3};"
        : "+f"(c0), "+f"(c1), "+f"(c2), "+f"(c3)
        : "r"(a0), "r"(a1), "r"(a2), "r"(a3), "r"(b0), "r"(b1));
}
__device__ __forceinline__ float fexp(float x) {   // FMA-pipe exp
    float y = fmaxf(x * 1.4426950408889634f, -80.0f);
    float t = y + 12582912.0f;
    int   n = __float_as_int(t) - 0x4B400000;
    float r = y - (t - 12582912.0f);
    float p = 1.3333558e-3f;
    p = fmaf(p, r, 9.6181291e-3f);
    p = fmaf(p, r, 5.5504109e-2f);
    p = fmaf(p, r, 2.4022651e-1f);
    p = fmaf(p, r, 6.9314718e-1f);
    p = fmaf(p, r, 1.0f);
    return __int_as_float(__float_as_int(p) + (n << 23));
}

// ---------------- fused fp32 -> fp16 converts ----------------
#define N4_X  (PB * PN * PC / 4)
#define N4_WQ (3 * PC * PC / 4)
#define N4_WP (PC * PC / 4)

__global__ void __launch_bounds__(256)
f2h_all(const float* __restrict__ x, const float* __restrict__ wq,
        const float* __restrict__ wp,
        __half* __restrict__ xh, __half* __restrict__ wqh, __half* __restrict__ wph)
{
    int i = blockIdx.x * blockDim.x + threadIdx.x;
    const float* s; __half* d; int j;
    if (i < N4_X)                 { s = x;  d = xh;  j = i; }
    else if (i < N4_X + N4_WQ)    { s = wq; d = wqh; j = i - N4_X; }
    else if (i < N4_X + N4_WQ + N4_WP) { s = wp; d = wph; j = i - N4_X - N4_WQ; }
    else return;
    float4 v = ((const float4*)s)[j];
    ((__half2*)d)[j * 2]     = __floats2half2_rn(v.x, v.y);
    ((__half2*)d)[j * 2 + 1] = __floats2half2_rn(v.z, v.w);
}

// ---------------- fp16 cp.async GEMM, B^T layout (QKV + proj) ----------------
template<int BM, int BN, int BK, int STAGES, int OUTM>
__global__ void __launch_bounds__(256)
gemm_h(const __half* __restrict__ A, const __half* __restrict__ B,
       void* __restrict__ Cb, const float* __restrict__ bias,
       int M, int N, int K, int ldc,
       __half* __restrict__ qp, __half* __restrict__ kp, __half* __restrict__ vp)
{
    constexpr int BKP = BK + 8;
    constexpr int WM = 4, WN = 2;
    constexpr int WTM = BM / WM, WTN = BN / WN;
    constexpr int MT = WTM / 16, NTt = WTN / 8;
    constexpr int ASTG = BM * BKP, BSTG = BN * BKP;
    constexpr int TPR = BK / 8, RPP = 256 / TPR;
    constexpr int APASS = BM / RPP, BPASS = BN / RPP;

    extern __shared__ __half sm[];
    __half* Asm = sm;
    __half* Bsm = sm + (long)STAGES * ASTG;

    const int tid = threadIdx.x, warp = tid >> 5, lane = tid & 31;
    const int g = lane >> 2, c4 = lane & 3;
    const int wm = warp % WM, wn = warp / WM;
    const int m0 = blockIdx.y * BM, n0 = blockIdx.x * BN;

    float acc[MT][NTt][4];
    #pragma unroll
    for (int i = 0; i < MT; i++)
        #pragma unroll
        for (int j = 0; j < NTt; j++)
            #pragma unroll
            for (int r = 0; r < 4; r++) acc[i][j][r] = 0.0f;

    const int nk = K / BK;
    auto load_stage = [&](int st, int k0) {
        const int r = tid / TPR, kc = (tid % TPR) * 8;
        #pragma unroll
        for (int p = 0; p < APASS; p++)
            cp_async16(smem_u32(Asm + (long)st * ASTG + (r + p * RPP) * BKP + kc),
                       A + (long)(m0 + r + p * RPP) * K + k0 + kc);
        #pragma unroll
        for (int p = 0; p < BPASS; p++)
            cp_async16(smem_u32(Bsm + (long)st * BSTG + (r + p * RPP) * BKP + kc),
                       B + (long)(n0 + r + p * RPP) * K + k0 + kc);
    };
    auto compute_stage = [&](int st) {
        const __half* As = Asm + (long)st * ASTG;
        const __half* Bs = Bsm + (long)st * BSTG;
        #pragma unroll
        for (int kk = 0; kk < BK; kk += 16) {
            uint32_t afr[MT][4];
            #pragma unroll
            for (int mt = 0; mt < MT; mt++)
                ldmx4(afr[mt][0], afr[mt][1], afr[mt][2], afr[mt][3],
                      smem_u32(As + (wm * WTM + mt * 16 + (lane & 15)) * BKP + kk + ((lane >> 4) << 3)));
            uint32_t bfr[NTt][2];
            #pragma unroll
            for (int nt = 0; nt < NTt; nt++)
                ldmx2(bfr[nt][0], bfr[nt][1],
                      smem_u32(Bs + (wn * WTN + nt * 8 + (lane & 7)) * BKP + kk + (((lane >> 3) & 1) << 3)));
            #pragma unroll
            for (int mt = 0; mt < MT; mt++)
                #pragma unroll
                for (int nt = 0; nt < NTt; nt++)
                    mma_f16(acc[mt][nt][0], acc[mt][nt][1], acc[mt][nt][2], acc[mt][nt][3],
                            afr[mt][0], afr[mt][1], afr[mt][2], afr[mt][3],
                            bfr[nt][0], bfr[nt][1]);
        }
    };

    #pragma unroll
    for (int s = 0; s < STAGES - 1; s++) {
        if (s < nk) load_stage(s, s * BK);
        cp_commit();
    }
    for (int i = 0; i < nk; i++) {
        cp_wait<STAGES - 2>();
        __syncthreads();
        compute_stage(i % STAGES);
        const int nx = i + STAGES - 1;
        if (nx < nk) load_stage(nx % STAGES, nx * BK);
        cp_commit();
        __syncthreads();
    }

    if constexpr (OUTM == 0) {
        float* C = (float*)Cb;
        #pragma unroll
        for (int mt = 0; mt < MT; mt++) {
            const int row = m0 + wm * WTM + mt * 16 + g;
            #pragma unroll
            for (int nt = 0; nt < NTt; nt++) {
                const int col = n0 + wn * WTN + nt * 8 + c4 * 2;
                float b0 = 0.0f, b1 = 0.0f;
                if (bias) { b0 = bias[col]; b1 = bias[col + 1]; }
                *(float2*)(C + (long)row * ldc + col) =
                    make_float2(acc[mt][nt][0] + b0, acc[mt][nt][1] + b1);
                *(float2*)(C + (long)(row + 8) * ldc + col) =
                    make_float2(acc[mt][nt][2] + b0, acc[mt][nt][3] + b1);
            }
        }
    } else {
        #pragma unroll
        for (int mt = 0; mt < MT; mt++) {
            const int row = m0 + wm * WTM + mt * 16 + g;
            const int b = row >> 10, n = row & 1023;
            #pragma unroll
            for (int nt = 0; nt < NTt; nt++) {
                const int col = n0 + wn * WTN + nt * 8 + c4 * 2;
                const int s = col / PC, r2 = col % PC;
                const int h = r2 >> 6, d = r2 & 63;
                __half* dstb = (s == 0) ? qp : (s == 1) ? kp : vp;
                const float sc = (s == 0) ? PSCALE : 1.0f;
                const long base = (((long)(b * PH + h) << 10) + n) * PD + d;
                *(__half2*)(dstb + base) = __floats2half2_rn(acc[mt][nt][0] * sc, acc[mt][nt][1] * sc);
                *(__half2*)(dstb + base + 8L * PD) = __floats2half2_rn(acc[mt][nt][2] * sc, acc[mt][nt][3] * sc);
            }
        }
    }
}

// ---------------- Stage 1: QK + pre-mix + exp + row sums (unchanged) ----------------
#define S1_K0 55296
#define S1_E  165888
#define S1_SM 190464

__global__ void __launch_bounds__(256)
qk_exp(const __half* __restrict__ qh, const __half* __restrict__ kh,
       __half* __restrict__ eG, float* __restrict__ rsG,
       const float* __restrict__ W_l, const float* __restrict__ b_l)
{
    extern __shared__ char dyn[];
    __half* qT = (__half*)dyn;
    __half* kB[2] = { (__half*)(dyn + S1_K0), (__half*)(dyn + 2 * S1_K0) };
    __half* eS = (__half*)(dyn + S1_E);
    __shared__ float wl[144], bls[12];
    __shared__ float rs[12][32];

    const int tid = threadIdx.x, warp = tid >> 5, lane = tid & 31;
    const int c4 = lane & 3, r8 = lane >> 2;
    const int wA = warp & 3, wN = warp >> 2;
    const int n0 = blockIdx.x * 32, b = blockIdx.y;

    if (tid < 144) wl[tid] = W_l[tid];
    if (tid < 12)  bls[tid] = b_l[tid];
    for (int t = tid; t < 384; t += 256) ((float*)rs)[t] = 0.0f;

    #pragma unroll
    for (int it = 0; it < 12; it++) {
        int c = it * 256 + tid, h = c >> 8, rr = (c >> 3) & 31, cc = (c & 7) * 8;
        cp_async16(smem_u32(qT + (h * 32 + rr) * 72 + cc),
                   qh + (((long)(b * PH + h) << 10) + n0 + rr) * PD + cc);
    }
    cp_commit();

    auto loadk = [&](int mt, __half* buf) {
        #pragma unroll
        for (int it = 0; it < 12; it++) {
            int c = it * 256 + tid, h = c >> 8, rr = (c >> 3) & 31, cc = (c & 7) * 8;
            cp_async16(smem_u32(buf + (h * 32 + rr) * 72 + cc),
                       kh + (((long)(b * PH + h) << 10) + mt * 32 + rr) * PD + cc);
        }
    };
    loadk(0, kB[0]); cp_commit();

    float ps[12][2];
    #pragma unroll
    for (int g = 0; g < 12; g++) { ps[g][0] = 0.0f; ps[g][1] = 0.0f; }

    for (int mt = 0; mt < 32; mt++) {
        __half* cur = kB[mt & 1];
        if (mt + 1 < 32) { loadk(mt + 1, kB[(mt + 1) & 1]); cp_commit(); cp_wait<1>(); }
        else             { cp_wait<0>(); }
        __syncthreads();

        float acc[12][4];
        #pragma unroll
        for (int h = 0; h < 12; h++)
            #pragma unroll
            for (int r = 0; r < 4; r++) acc[h][r] = 0.0f;
        #pragma unroll
        for (int h = 0; h < 12; h++) {
            #pragma unroll
            for (int kc = 0; kc < 4; kc++) {
                uint32_t a0, a1, a2, a3, b0, b1;
                ldmx4(a0, a1, a2, a3,
                      smem_u32(qT + (h * 32 + wN * 16 + (lane & 15)) * 72 + kc * 16 + ((lane >> 4) << 3)));
                ldmx2(b0, b1,
                      smem_u32(cur + (h * 32 + wA * 8 + (lane & 7)) * 72 + kc * 16 + (((lane >> 3) & 1) << 3)));
                mma_f16(acc[h][0], acc[h][1], acc[h][2], acc[h][3], a0, a1, a2, a3, b0, b1);
            }
        }
        #pragma unroll
        for (int g = 0; g < 12; g++) {
            float t0 = bls[g], t1 = t0, t2 = t0, t3 = t0;
            #pragma unroll
            for (int h = 0; h < 12; h++) {
                const float w = wl[g * 12 + h];
                t0 = fmaf(w, acc[h][0], t0); t1 = fmaf(w, acc[h][1], t1);
                t2 = fmaf(w, acc[h][2], t2); t3 = fmaf(w, acc[h][3], t3);
            }
            const float e0 = fexp(t0), e1 = fexp(t1), e2 = fexp(t2), e3 = fexp(t3);
            ps[g][0] += e0 + e1; ps[g][1] += e2 + e3;
            const int mcol = wA * 8 + c4 * 2;
            *(__half2*)(eS + (g * 32 + wN * 16 + r8) * 32 + mcol)     = __floats2half2_rn(e0, e1);
            *(__half2*)(eS + (g * 32 + wN * 16 + r8 + 8) * 32 + mcol) = __floats2half2_rn(e2, e3);
        }
        __syncthreads();
        #pragma unroll
        for (int j = 0; j < 6; j++) {
            int c = tid + j * 256, h = c >> 7, nn = (c >> 2) & 31, q4 = c & 3;
            float4 v = *(float4*)(eS + (h * 32 + nn) * 32 + q4 * 8);
            *(float4*)(eG + ((long)(b * PH + h) << 20) + ((long)(n0 + nn) << 10) + mt * 32 + q4 * 8) = v;
        }
    }
    #pragma unroll
    for (int g = 0; g < 12; g++)
        #pragma unroll
        for (int q = 0; q < 2; q++) {
            ps[g][q] += __shfl_xor_sync(0xFFFFFFFFu, ps[g][q], 1);
            ps[g][q] += __shfl_xor_sync(0xFFFFFFFFu, ps[g][q], 2);
        }
    __syncthreads();
    if (c4 == 0) {
        #pragma unroll
        for (int g = 0; g < 12; g++) {
            atomicAdd(&rs[g][wN * 16 + r8],     ps[g][0]);
            atomicAdd(&rs[g][wN * 16 + r8 + 8], ps[g][1]);
        }
    }
    __syncthreads();
    for (int t = tid; t < 384; t += 256) {
        int h = t >> 5, nn = t & 31;
        rsG[((long)(b * PH + h) << 10) + n0 + nn] = rs[h][nn];
    }
}

// ---------------- Stage 2 v6: tensor-core mix + PV, eB skewed per-head ----------------
// eB row-block stride per head = 1288 halves (32*40 + 8): mix ldmx2t rows land
// 2576B apart == 16 mod 128 -> 2-way conflict instead of 16-way.
// aS [12g][32nn][40m] + g*8 halves skew (unchanged). vS [12][32][72]. W2 [32nn][16g][24h].
#define EH 1288
#define S5_EB1 41216
#define S5_AS  82432
#define S5_V   113408
#define S5_W2  168704
#define S5_SM  193280

__global__ void __launch_bounds__(512)
mix_pv(const __half* __restrict__ eG, const __half* __restrict__ vh,
       const float* __restrict__ rsG, __half* __restrict__ oh,
       const float* __restrict__ W_w, const float* __restrict__ b_w,
       const float* __restrict__ lamb)
{
    extern __shared__ char dyn[];
    __half* eB[2] = { (__half*)dyn, (__half*)(dyn + S5_EB1) };
    __half* aS = (__half*)(dyn + S5_AS);
    __half* vS = (__half*)(dyn + S5_V);
    __half* W2 = (__half*)(dyn + S5_W2);
    __shared__ float wp[144], cg[12], invS[12][32];

    const int tid = threadIdx.x, warp = tid >> 5, lane = tid & 31;
    const int c4 = lane & 3, r8 = lane >> 2;
    const int wg = warp >> 3, w8 = warp & 7;       // PV: head-group, d-slice
    const int n0 = blockIdx.x * 32, b = blockIdx.y;

    if (tid < 144) wp[tid] = W_w[tid] * (1.0f + lamb[tid / 12]);
    if (tid < 12) { const float ad = 1.0f / 1024.0f; cg[tid] = ad + (b_w[tid] - ad) * (1.0f + lamb[tid]); }
    if (tid < 384) {
        int hh = tid >> 5, nn = tid & 31;
        invS[hh][nn] = 1.0f / rsG[((long)(b * PH + hh) << 10) + n0 + nn];
    }
    __syncthreads();

    // W2[nn][g][h]: h<12 -> wp*invS; h==12 -> cg (bias channel); else 0. g>=12 rows zero.
    for (int t = tid; t < 8192; t += 512) {
        int nn = t >> 8, g = (t >> 4) & 15, h = t & 15;
        float v = 0.0f;
        if (g < 12) { if (h < 12) v = wp[g * 12 + h] * invS[h][nn]; else if (h == 12) v = cg[g]; }
        W2[nn * 384 + g * 24 + h] = __float2half_rn(v);
    }
    // eB pad head-blocks h=12..15 (both buffers): h12 = 1.0 (bias), rest 0
    for (int t = tid; t < 10240; t += 512) {
        int buf = t >= 5120, u = t % 5120;
        int h = 12 + u / 1280, rem = u % 1280, nn = rem / 40, m = rem % 40;
        eB[buf][h * EH + nn * 40 + m] = __float2half_rn(h == 12 ? 1.0f : 0.0f);
    }

    auto loadE = [&](int mt, __half* buf) {
        #pragma unroll
        for (int j = 0; j < 3; j++) {                 // 12*32*4 = 1536 chunks
            int c = tid + j * 512, hh = c >> 7, nn = (c >> 2) & 31, q4 = c & 3;
            cp_async16(smem_u32(buf + hh * EH + nn * 40 + q4 * 8),
                       eG + ((long)(b * PH + hh) << 20) + ((long)(n0 + nn) << 10) + mt * 32 + q4 * 8);
        }
    };
    auto loadV = [&](int mt) {
        #pragma unroll
        for (int j = 0; j < 6; j++) {                 // 12*32*8 = 3072 chunks
            int c = tid + j * 512, hh = c >> 8, rr = (c >> 3) & 31, cc = (c & 7) * 8;
            cp_async16(smem_u32(vS + (hh * 32 + rr) * 72 + cc),
                       vh + (((long)(b * PH + hh) << 10) + mt * 32 + rr) * PD + cc);
        }
    };

    float acc[6][2][4];                               // 6 heads (group wg) x 2 row-halves
    #pragma unroll
    for (int h = 0; h < 6; h++)
        #pragma unroll
        for (int f = 0; f < 2; f++)
            #pragma unroll
            for (int r = 0; r < 4; r++) acc[h][f][r] = 0.0f;

    loadE(0, eB[0]); loadV(0); cp_commit();

    for (int mt = 0; mt < 32; mt++) {
        __half* ec = eB[mt & 1];
        if (mt + 1 < 32) { loadE(mt + 1, eB[(mt + 1) & 1]); cp_commit(); cp_wait<1>(); }
        else             { cp_wait<0>(); }
        __syncthreads();   // E(mt)+V(mt) ready; W2/pads ready (first iter)

        // ---- MIX via tensor cores: warp handles nn = warp, warp+16 ----
        #pragma unroll
        for (int j = 0; j < 2; j++) {
            const int nn = warp + 16 * j;
            uint32_t A0, A1, A2, A3;
            ldmx4(A0, A1, A2, A3,
                  smem_u32(W2 + nn * 384 + (lane & 15) * 24 + ((lane >> 4) << 3)));
            #pragma unroll
            for (int ms = 0; ms < 4; ms++) {
                uint32_t B0, B1;
                ldmx2t(B0, B1, smem_u32(ec + (lane & 15) * EH + nn * 40 + ms * 8));
                float d0 = 0.0f, d1 = 0.0f, d2 = 0.0f, d3 = 0.0f;
                mma_f16(d0, d1, d2, d3, A0, A1, A2, A3, B0, B1);
                const int m = ms * 8 + c4 * 2;
                *(__half2*)(aS + (r8 * 32 + nn) * 40 + r8 * 8 + m) = __floats2half2_rn(d0, d1);
                if (r8 < 4)
                    *(__half2*)(aS + ((r8 + 8) * 32 + nn) * 40 + (r8 + 8) * 8 + m) = __floats2half2_rn(d2, d3);
            }
        }
        __syncthreads();   // aS ready

        // ---- PV: warp (wg, w8) -> heads wg*6..+6, d-slice w8*8 ----
        #pragma unroll
        for (int hh = 0; hh < 6; hh++) {
            const int h = wg * 6 + hh;
            #pragma unroll
            for (int kc = 0; kc < 2; kc++) {
                uint32_t b0, b1;
                ldmx2t(b0, b1, smem_u32(vS + (h * 32 + kc * 16 + (lane & 15)) * 72 + w8 * 8));
                #pragma unroll
                for (int f = 0; f < 2; f++) {
                    uint32_t a0, a1, a2, a3;
                    ldmx4(a0, a1, a2, a3,
                          smem_u32(aS + (h * 32 + f * 16 + (lane & 15)) * 40 + h * 8 + kc * 16 + ((lane >> 4) << 3)));
                    mma_f16(acc[hh][f][0], acc[hh][f][1], acc[hh][f][2], acc[hh][f][3],
                            a0, a1, a2, a3, b0, b1);
                }
            }
        }
        __syncthreads();   // PV reads done

        if (mt + 1 < 32) { loadV(mt + 1); cp_commit(); }
    }

    #pragma unroll
    for (int hh = 0; hh < 6; hh++) {
        const int h = wg * 6 + hh;
        #pragma unroll
        for (int f = 0; f < 2; f++) {
            const long base = ((long)((b << 10) + n0 + f * 16 + r8)) * PC + h * 64 + w8 * 8 + c4 * 2;
            *(__half2*)(oh + base)           = __floats2half2_rn(acc[hh][f][0], acc[hh][f][1]);
            *(__half2*)(oh + base + 8L * PC) = __floats2half2_rn(acc[hh][f][2], acc[hh][f][3]);
        }
    }
}

// ---------------- launcher ----------------
extern "C" void kernel_launch(void* const* d_in, const int* in_sizes, int n_in,
                              void* d_out, int out_size)
{
    const float* x      = (const float*)d_in[0];
    const float* W_qkv  = (const float*)d_in[1];
    const float* W_proj = (const float*)d_in[2];
    const float* b_proj = (const float*)d_in[3];
    const float* W_l    = (const float*)d_in[4];
    const float* b_l    = (const float*)d_in[5];
    const float* W_w    = (const float*)d_in[6];
    const float* b_w    = (const float*)d_in[7];
    const float* lamb   = (const float*)d_in[8];
    float* out = (float*)d_out;

    __half *xh, *wqh, *wph, *qh, *kh, *vh, *e, *oh;
    float *rs;
    cudaGetSymbolAddress((void**)&xh,  g_xh);
    cudaGetSymbolAddress((void**)&wqh, g_wqh);
    cudaGetSymbolAddress((void**)&wph, g_wph);
    cudaGetSymbolAddress((void**)&qh,  g_qh);
    cudaGetSymbolAddress((void**)&kh,  g_kh);
    cudaGetSymbolAddress((void**)&vh,  g_vh);
    cudaGetSymbolAddress((void**)&e,   g_e);
    cudaGetSymbolAddress((void**)&rs,  g_rs);
    cudaGetSymbolAddress((void**)&oh,  g_oh);

    const int M = PB * PN;
    constexpr int SM_G = 3 * 2 * 128 * 72 * 2;   // 110592 (BK=64, 3 stages)

    {   const int total = N4_X + N4_WQ + N4_WP;
        f2h_all<<<(total + 255) / 256, 256>>>(x, W_qkv, W_proj, xh, wqh, wph);
    }
    {   auto kfn = gemm_h<128, 128, 64, 3, 2>;
        cudaFuncSetAttribute(kfn, cudaFuncAttributeMaxDynamicSharedMemorySize, SM_G);
        dim3 grid(3 * PC / 128, M / 128, 1);
        kfn<<<grid, 256, SM_G>>>(xh, wqh, nullptr, nullptr, M, 3 * PC, PC, 0, qh, kh, vh);
    }
    {   cudaFuncSetAttribute(qk_exp, cudaFuncAttributeMaxDynamicSharedMemorySize, S1_SM);
        dim3 grid(PN / 32, PB, 1);
        qk_exp<<<grid, 256, S1_SM>>>(qh, kh, e, rs, W_l, b_l);
    }
    {   cudaFuncSetAttribute(mix_pv, cudaFuncAttributeMaxDynamicSharedMemorySize, S5_SM);
        dim3 grid(PN / 32, PB, 1);
        mix_pv<<<grid, 512, S5_SM>>>(e, vh, rs, oh, W_w, b_w, lamb);
    }
    {   auto kfn = gemm_h<128, 128, 64, 3, 0>;
        cudaFuncSetAttribute(kfn, cudaFuncAttributeMaxDynamicSharedMemorySize, SM_G);
        dim3 grid(PC / 128, M / 128, 1);
        kfn<<<grid, 256, SM_G>>>(oh, wph, out, b_proj, M, PC, PC, PC, nullptr, nullptr, nullptr);
    }
}

// round 17
// speedup vs baseline: 1.5542x; 1.0231x over previous
#include <cuda_runtime.h>
#include <cuda_fp16.h>
#include <math.h>
#include <stdint.h>

#define PB 4
#define PN 1024
#define PC 768
#define PH 12
#define PD 64
#define PSCALE 0.125f

// ---------------- scratch ----------------
__device__ __half g_xh[(long)PB * PN * PC];
__device__ __half g_wqh[(long)3 * PC * PC];
__device__ __half g_wph[(long)PC * PC];
__device__ __half g_qh[(long)PB * PH * PN * PD];
__device__ __half g_kh[(long)PB * PH * PN * PD];
__device__ __half g_vh[(long)PB * PH * PN * PD];
__device__ __half g_e [(long)PB * PH * PN * PN];   // 100 MB unnormalized exp scores
__device__ float  g_rs[(long)PB * PH * PN];        // row sums
__device__ __half g_oh[(long)PB * PN * PC];

__device__ __forceinline__ uint32_t smem_u32(const void* p) {
    return (uint32_t)__cvta_generic_to_shared(p);
}
__device__ __forceinline__ void cp_async16(uint32_t dst, const void* src) {
    asm volatile("cp.async.cg.shared.global [%0], [%1], 16;" :: "r"(dst), "l"(src));
}
__device__ __forceinline__ void cp_commit() { asm volatile("cp.async.commit_group;"); }
template<int N_> __device__ __forceinline__ void cp_wait() {
    asm volatile("cp.async.wait_group %0;" :: "n"(N_));
}
__device__ __forceinline__ void ldmx4(uint32_t& r0, uint32_t& r1, uint32_t& r2, uint32_t& r3, uint32_t a) {
    asm volatile("ldmatrix.sync.aligned.m8n8.x4.shared.b16 {%0,%1,%2,%3}, [%4];"
                 : "=r"(r0), "=r"(r1), "=r"(r2), "=r"(r3) : "r"(a));
}
__device__ __forceinline__ void ldmx2(uint32_t& r0, uint32_t& r1, uint32_t a) {
    asm volatile("ldmatrix.sync.aligned.m8n8.x2.shared.b16 {%0,%1}, [%2];"
                 : "=r"(r0), "=r"(r1) : "r"(a));
}
__device__ __forceinline__ void ldmx2t(uint32_t& r0, uint32_t& r1, uint32_t a) {
    asm volatile("ldmatrix.sync.aligned.m8n8.x2.trans.shared.b16 {%0,%1}, [%2];"
                 : "=r"(r0), "=r"(r1) : "r"(a));
}
__device__ __forceinline__ void mma_f16(float& c0, float& c1, float& c2, float& c3,
                                        uint32_t a0, uint32_t a1, uint32_t a2, uint32_t a3,
                                        uint32_t b0, uint32_t b1) {
    asm volatile(
        "mma.sync.aligned.m16n8k16.row.col.f32.f16.f16.f32 "
        "{%0,%1,%2,%3}, {%4,%5,%6,%7}, {%8,%9}, {%0,%1,%2,%3};"
        : "+f"(c0), "+f"(c1), "+f"(c2), "+f"(c3)
        : "r"(a0), "r"(a1), "r"(a2), "r"(a3), "r"(b0), "r"(b1));
}

// ---------------- fused fp32 -> fp16 converts ----------------
#define N4_X  (PB * PN * PC / 4)
#define N4_WQ (3 * PC * PC / 4)
#define N4_WP (PC * PC / 4)

__global__ void __launch_bounds__(256)
f2h_all(const float* __restrict__ x, const float* __restrict__ wq,
        const float* __restrict__ wp,
        __half* __restrict__ xh, __half* __restrict__ wqh, __half* __restrict__ wph)
{
    int i = blockIdx.x * blockDim.x + threadIdx.x;
    const float* s; __half* d; int j;
    if (i < N4_X)                 { s = x;  d = xh;  j = i; }
    else if (i < N4_X + N4_WQ)    { s = wq; d = wqh; j = i - N4_X; }
    else if (i < N4_X + N4_WQ + N4_WP) { s = wp; d = wph; j = i - N4_X - N4_WQ; }
    else return;
    float4 v = ((const float4*)s)[j];
    ((__half2*)d)[j * 2]     = __floats2half2_rn(v.x, v.y);
    ((__half2*)d)[j * 2 + 1] = __floats2half2_rn(v.z, v.w);
}

// ---------------- fp16 cp.async GEMM, B^T layout (QKV + proj) ----------------
template<int BM, int BN, int BK, int STAGES, int OUTM>
__global__ void __launch_bounds__(256)
gemm_h(const __half* __restrict__ A, const __half* __restrict__ B,
       void* __restrict__ Cb, const float* __restrict__ bias,
       int M, int N, int K, int ldc,
       __half* __restrict__ qp, __half* __restrict__ kp, __half* __restrict__ vp)
{
    constexpr int BKP = BK + 8;
    constexpr int WM = 4, WN = 2;
    constexpr int WTM = BM / WM, WTN = BN / WN;
    constexpr int MT = WTM / 16, NTt = WTN / 8;
    constexpr int ASTG = BM * BKP, BSTG = BN * BKP;
    constexpr int TPR = BK / 8, RPP = 256 / TPR;
    constexpr int APASS = BM / RPP, BPASS = BN / RPP;

    extern __shared__ __half sm[];
    __half* Asm = sm;
    __half* Bsm = sm + (long)STAGES * ASTG;

    const int tid = threadIdx.x, warp = tid >> 5, lane = tid & 31;
    const int g = lane >> 2, c4 = lane & 3;
    const int wm = warp % WM, wn = warp / WM;
    const int m0 = blockIdx.y * BM, n0 = blockIdx.x * BN;

    float acc[MT][NTt][4];
    #pragma unroll
    for (int i = 0; i < MT; i++)
        #pragma unroll
        for (int j = 0; j < NTt; j++)
            #pragma unroll
            for (int r = 0; r < 4; r++) acc[i][j][r] = 0.0f;

    const int nk = K / BK;
    auto load_stage = [&](int st, int k0) {
        const int r = tid / TPR, kc = (tid % TPR) * 8;
        #pragma unroll
        for (int p = 0; p < APASS; p++)
            cp_async16(smem_u32(Asm + (long)st * ASTG + (r + p * RPP) * BKP + kc),
                       A + (long)(m0 + r + p * RPP) * K + k0 + kc);
        #pragma unroll
        for (int p = 0; p < BPASS; p++)
            cp_async16(smem_u32(Bsm + (long)st * BSTG + (r + p * RPP) * BKP + kc),
                       B + (long)(n0 + r + p * RPP) * K + k0 + kc);
    };
    auto compute_stage = [&](int st) {
        const __half* As = Asm + (long)st * ASTG;
        const __half* Bs = Bsm + (long)st * BSTG;
        #pragma unroll
        for (int kk = 0; kk < BK; kk += 16) {
            uint32_t afr[MT][4];
            #pragma unroll
            for (int mt = 0; mt < MT; mt++)
                ldmx4(afr[mt][0], afr[mt][1], afr[mt][2], afr[mt][3],
                      smem_u32(As + (wm * WTM + mt * 16 + (lane & 15)) * BKP + kk + ((lane >> 4) << 3)));
            uint32_t bfr[NTt][2];
            #pragma unroll
            for (int nt = 0; nt < NTt; nt++)
                ldmx2(bfr[nt][0], bfr[nt][1],
                      smem_u32(Bs + (wn * WTN + nt * 8 + (lane & 7)) * BKP + kk + (((lane >> 3) & 1) << 3)));
            #pragma unroll
            for (int mt = 0; mt < MT; mt++)
                #pragma unroll
                for (int nt = 0; nt < NTt; nt++)
                    mma_f16(acc[mt][nt][0], acc[mt][nt][1], acc[mt][nt][2], acc[mt][nt][3],
                            afr[mt][0], afr[mt][1], afr[mt][2], afr[mt][3],
                            bfr[nt][0], bfr[nt][1]);
        }
    };

    #pragma unroll
    for (int s = 0; s < STAGES - 1; s++) {
        if (s < nk) load_stage(s, s * BK);
        cp_commit();
    }
    for (int i = 0; i < nk; i++) {
        cp_wait<STAGES - 2>();
        __syncthreads();
        compute_stage(i % STAGES);
        const int nx = i + STAGES - 1;
        if (nx < nk) load_stage(nx % STAGES, nx * BK);
        cp_commit();
        __syncthreads();
    }

    if constexpr (OUTM == 0) {
        float* C = (float*)Cb;
        #pragma unroll
        for (int mt = 0; mt < MT; mt++) {
            const int row = m0 + wm * WTM + mt * 16 + g;
            #pragma unroll
            for (int nt = 0; nt < NTt; nt++) {
                const int col = n0 + wn * WTN + nt * 8 + c4 * 2;
                float b0 = 0.0f, b1 = 0.0f;
                if (bias) { b0 = bias[col]; b1 = bias[col + 1]; }
                *(float2*)(C + (long)row * ldc + col) =
                    make_float2(acc[mt][nt][0] + b0, acc[mt][nt][1] + b1);
                *(float2*)(C + (long)(row + 8) * ldc + col) =
                    make_float2(acc[mt][nt][2] + b0, acc[mt][nt][3] + b1);
            }
        }
    } else {
        #pragma unroll
        for (int mt = 0; mt < MT; mt++) {
            const int row = m0 + wm * WTM + mt * 16 + g;
            const int b = row >> 10, n = row & 1023;
            #pragma unroll
            for (int nt = 0; nt < NTt; nt++) {
                const int col = n0 + wn * WTN + nt * 8 + c4 * 2;
                const int s = col / PC, r2 = col % PC;
                const int h = r2 >> 6, d = r2 & 63;
                __half* dstb = (s == 0) ? qp : (s == 1) ? kp : vp;
                const float sc = (s == 0) ? PSCALE : 1.0f;
                const long base = (((long)(b * PH + h) << 10) + n) * PD + d;
                *(__half2*)(dstb + base) = __floats2half2_rn(acc[mt][nt][0] * sc, acc[mt][nt][1] * sc);
                *(__half2*)(dstb + base + 8L * PD) = __floats2half2_rn(acc[mt][nt][2] * sc, acc[mt][nt][3] * sc);
            }
        }
    }
}

// ---------------- Stage 1: QK + pre-mix + exp + row sums (exp -> MUFU) ----------------
#define S1_K0 55296
#define S1_E  165888
#define S1_SM 190464

__global__ void __launch_bounds__(256)
qk_exp(const __half* __restrict__ qh, const __half* __restrict__ kh,
       __half* __restrict__ eG, float* __restrict__ rsG,
       const float* __restrict__ W_l, const float* __restrict__ b_l)
{
    extern __shared__ char dyn[];
    __half* qT = (__half*)dyn;
    __half* kB[2] = { (__half*)(dyn + S1_K0), (__half*)(dyn + 2 * S1_K0) };
    __half* eS = (__half*)(dyn + S1_E);
    __shared__ float wl[144], bls[12];
    __shared__ float rs[12][32];

    const int tid = threadIdx.x, warp = tid >> 5, lane = tid & 31;
    const int c4 = lane & 3, r8 = lane >> 2;
    const int wA = warp & 3, wN = warp >> 2;
    const int n0 = blockIdx.x * 32, b = blockIdx.y;

    if (tid < 144) wl[tid] = W_l[tid];
    if (tid < 12)  bls[tid] = b_l[tid];
    for (int t = tid; t < 384; t += 256) ((float*)rs)[t] = 0.0f;

    #pragma unroll
    for (int it = 0; it < 12; it++) {
        int c = it * 256 + tid, h = c >> 8, rr = (c >> 3) & 31, cc = (c & 7) * 8;
        cp_async16(smem_u32(qT + (h * 32 + rr) * 72 + cc),
                   qh + (((long)(b * PH + h) << 10) + n0 + rr) * PD + cc);
    }
    cp_commit();

    auto loadk = [&](int mt, __half* buf) {
        #pragma unroll
        for (int it = 0; it < 12; it++) {
            int c = it * 256 + tid, h = c >> 8, rr = (c >> 3) & 31, cc = (c & 7) * 8;
            cp_async16(smem_u32(buf + (h * 32 + rr) * 72 + cc),
                       kh + (((long)(b * PH + h) << 10) + mt * 32 + rr) * PD + cc);
        }
    };
    loadk(0, kB[0]); cp_commit();

    float ps[12][2];
    #pragma unroll
    for (int g = 0; g < 12; g++) { ps[g][0] = 0.0f; ps[g][1] = 0.0f; }

    for (int mt = 0; mt < 32; mt++) {
        __half* cur = kB[mt & 1];
        if (mt + 1 < 32) { loadk(mt + 1, kB[(mt + 1) & 1]); cp_commit(); cp_wait<1>(); }
        else             { cp_wait<0>(); }
        __syncthreads();

        float acc[12][4];
        #pragma unroll
        for (int h = 0; h < 12; h++)
            #pragma unroll
            for (int r = 0; r < 4; r++) acc[h][r] = 0.0f;
        #pragma unroll
        for (int h = 0; h < 12; h++) {
            #pragma unroll
            for (int kc = 0; kc < 4; kc++) {
                uint32_t a0, a1, a2, a3, b0, b1;
                ldmx4(a0, a1, a2, a3,
                      smem_u32(qT + (h * 32 + wN * 16 + (lane & 15)) * 72 + kc * 16 + ((lane >> 4) << 3)));
                ldmx2(b0, b1,
                      smem_u32(cur + (h * 32 + wA * 8 + (lane & 7)) * 72 + kc * 16 + (((lane >> 3) & 1) << 3)));
                mma_f16(acc[h][0], acc[h][1], acc[h][2], acc[h][3], a0, a1, a2, a3, b0, b1);
            }
        }
        #pragma unroll
        for (int g = 0; g < 12; g++) {
            float t0 = bls[g], t1 = t0, t2 = t0, t3 = t0;
            #pragma unroll
            for (int h = 0; h < 12; h++) {
                const float w = wl[g * 12 + h];
                t0 = fmaf(w, acc[h][0], t0); t1 = fmaf(w, acc[h][1], t1);
                t2 = fmaf(w, acc[h][2], t2); t3 = fmaf(w, acc[h][3], t3);
            }
            const float e0 = __expf(t0), e1 = __expf(t1), e2 = __expf(t2), e3 = __expf(t3);
            ps[g][0] += e0 + e1; ps[g][1] += e2 + e3;
            const int mcol = wA * 8 + c4 * 2;
            *(__half2*)(eS + (g * 32 + wN * 16 + r8) * 32 + mcol)     = __floats2half2_rn(e0, e1);
            *(__half2*)(eS + (g * 32 + wN * 16 + r8 + 8) * 32 + mcol) = __floats2half2_rn(e2, e3);
        }
        __syncthreads();
        #pragma unroll
        for (int j = 0; j < 6; j++) {
            int c = tid + j * 256, h = c >> 7, nn = (c >> 2) & 31, q4 = c & 3;
            float4 v = *(float4*)(eS + (h * 32 + nn) * 32 + q4 * 8);
            *(float4*)(eG + ((long)(b * PH + h) << 20) + ((long)(n0 + nn) << 10) + mt * 32 + q4 * 8) = v;
        }
    }
    #pragma unroll
    for (int g = 0; g < 12; g++)
        #pragma unroll
        for (int q = 0; q < 2; q++) {
            ps[g][q] += __shfl_xor_sync(0xFFFFFFFFu, ps[g][q], 1);
            ps[g][q] += __shfl_xor_sync(0xFFFFFFFFu, ps[g][q], 2);
        }
    __syncthreads();
    if (c4 == 0) {
        #pragma unroll
        for (int g = 0; g < 12; g++) {
            atomicAdd(&rs[g][wN * 16 + r8],     ps[g][0]);
            atomicAdd(&rs[g][wN * 16 + r8 + 8], ps[g][1]);
        }
    }
    __syncthreads();
    for (int t = tid; t < 384; t += 256) {
        int h = t >> 5, nn = t & 31;
        rsG[((long)(b * PH + h) << 10) + n0 + nn] = rs[h][nn];
    }
}

// ---------------- Stage 2 v7: in-place normalize + single W2 + 2-barrier loop ----------------
// eB double, per-head stride EH=1288 (2-way conflicts). invS folded into E (per-warp,
// warp-private: each warp scales only its own nn columns). W2 single [16g][24h] (768B).
// aS [12g][32nn][40m] + g*8 skew. vS DOUBLE-buffered. Loads for mt+1 overlap PV(mt).
#define EH 1288
#define S6_EB1 41216
#define S6_AS  82432
#define S6_V0  113408
#define S6_VST 55296
#define S6_W2  224000
#define S6_SM  224768

__global__ void __launch_bounds__(512)
mix_pv(const __half* __restrict__ eG, const __half* __restrict__ vh,
       const float* __restrict__ rsG, __half* __restrict__ oh,
       const float* __restrict__ W_w, const float* __restrict__ b_w,
       const float* __restrict__ lamb)
{
    extern __shared__ char dyn[];
    __half* eB[2] = { (__half*)dyn, (__half*)(dyn + S6_EB1) };
    __half* aS = (__half*)(dyn + S6_AS);
    __half* vB[2] = { (__half*)(dyn + S6_V0), (__half*)(dyn + S6_V0 + S6_VST) };
    __half* W2 = (__half*)(dyn + S6_W2);
    __shared__ float invS[12][32];

    const int tid = threadIdx.x, warp = tid >> 5, lane = tid & 31;
    const int c4 = lane & 3, r8 = lane >> 2;
    const int wg = warp >> 3, w8 = warp & 7;       // PV: head-group, d-slice
    const int n0 = blockIdx.x * 32, b = blockIdx.y;

    if (tid < 384) {
        int hh = tid >> 5, nn = tid & 31;
        invS[hh][nn] = 1.0f / rsG[((long)(b * PH + hh) << 10) + n0 + nn];
    }
    // W2[g][h]: g<12,h<12 -> W_w*(1+lamb); h==12 -> cg; else 0.  (single 16x24)
    if (tid < 384) {
        int g = tid / 24, h = tid % 24;
        float v = 0.0f;
        if (g < 12) {
            if (h < 12) v = W_w[g * 12 + h] * (1.0f + lamb[g]);
            else if (h == 12) {
                const float ad = 1.0f / 1024.0f;
                v = ad + (b_w[g] - ad) * (1.0f + lamb[g]);
            }
        }
        W2[tid] = __float2half_rn(v);
    }
    // eB pad head-blocks h=12..15 (both buffers): h12 = 1.0 (bias), rest 0
    for (int t = tid; t < 10240; t += 512) {
        int buf = t >= 5120, u = t % 5120;
        int h = 12 + u / 1280, rem = u % 1280, nn = rem / 40, m = rem % 40;
        eB[buf][h * EH + nn * 40 + m] = __float2half_rn(h == 12 ? 1.0f : 0.0f);
    }

    auto loadE = [&](int mt, __half* buf) {
        #pragma unroll
        for (int j = 0; j < 3; j++) {                 // 12*32*4 = 1536 chunks
            int c = tid + j * 512, hh = c >> 7, nn = (c >> 2) & 31, q4 = c & 3;
            cp_async16(smem_u32(buf + hh * EH + nn * 40 + q4 * 8),
                       eG + ((long)(b * PH + hh) << 20) + ((long)(n0 + nn) << 10) + mt * 32 + q4 * 8);
        }
    };
    auto loadV = [&](int mt, __half* buf) {
        #pragma unroll
        for (int j = 0; j < 6; j++) {                 // 12*32*8 = 3072 chunks
            int c = tid + j * 512, hh = c >> 8, rr = (c >> 3) & 31, cc = (c & 7) * 8;
            cp_async16(smem_u32(buf + (hh * 32 + rr) * 72 + cc),
                       vh + (((long)(b * PH + hh) << 10) + mt * 32 + rr) * PD + cc);
        }
    };

    float acc[6][2][4];
    #pragma unroll
    for (int h = 0; h < 6; h++)
        #pragma unroll
        for (int f = 0; f < 2; f++)
            #pragma unroll
            for (int r = 0; r < 4; r++) acc[h][f][r] = 0.0f;

    loadE(0, eB[0]); loadV(0, vB[0]); cp_commit();
    __syncthreads();                                  // W2 + pads + invS ready

    // hoisted mix A-fragment (constant across all iterations)
    uint32_t A0, A1, A2, A3;
    ldmx4(A0, A1, A2, A3, smem_u32(W2 + (lane & 15) * 24 + ((lane >> 4) << 3)));

    for (int mt = 0; mt < 32; mt++) {
        __half* ec = eB[mt & 1];
        __half* vc = vB[mt & 1];
        cp_wait<0>();
        __syncthreads();   // E(mt)+V(mt) in smem; all threads past PV(mt-1)

        // ---- MIX: per-warp normalize own nn columns, then mma ----
        #pragma unroll
        for (int j = 0; j < 2; j++) {
            const int nn = warp + 16 * j;
            #pragma unroll
            for (int k = 0; k < 6; k++) {             // 12h x 16 half2 = 192 items
                const int idx = lane + 32 * k;
                const int h = idx >> 4, mp = idx & 15;
                __half2* p = (__half2*)(ec + h * EH + nn * 40 + mp * 2);
                float2 v = __half22float2(*p);
                const float iv = invS[h][nn];
                *p = __floats2half2_rn(v.x * iv, v.y * iv);
            }
            __syncwarp();
            #pragma unroll
            for (int ms = 0; ms < 4; ms++) {
                uint32_t B0, B1;
                ldmx2t(B0, B1, smem_u32(ec + (lane & 15) * EH + nn * 40 + ms * 8));
                float d0 = 0.0f, d1 = 0.0f, d2 = 0.0f, d3 = 0.0f;
                mma_f16(d0, d1, d2, d3, A0, A1, A2, A3, B0, B1);
                const int m = ms * 8 + c4 * 2;
                *(__half2*)(aS + (r8 * 32 + nn) * 40 + r8 * 8 + m) = __floats2half2_rn(d0, d1);
                if (r8 < 4)
                    *(__half2*)(aS + ((r8 + 8) * 32 + nn) * 40 + (r8 + 8) * 8 + m) = __floats2half2_rn(d2, d3);
            }
        }
        __syncthreads();   // aS ready; eB[cur] mix reads done

        // prefetch next tile into alternate buffers; overlaps with PV below
        if (mt + 1 < 32) { loadE(mt + 1, eB[(mt + 1) & 1]); loadV(mt + 1, vB[(mt + 1) & 1]); cp_commit(); }

        // ---- PV: warp (wg, w8) -> heads wg*6..+6, d-slice w8*8 ----
        #pragma unroll
        for (int hh = 0; hh < 6; hh++) {
            const int h = wg * 6 + hh;
            #pragma unroll
            for (int kc = 0; kc < 2; kc++) {
                uint32_t b0, b1;
                ldmx2t(b0, b1, smem_u32(vc + (h * 32 + kc * 16 + (lane & 15)) * 72 + w8 * 8));
                #pragma unroll
                for (int f = 0; f < 2; f++) {
                    uint32_t a0, a1, a2, a3;
                    ldmx4(a0, a1, a2, a3,
                          smem_u32(aS + (h * 32 + f * 16 + (lane & 15)) * 40 + h * 8 + kc * 16 + ((lane >> 4) << 3)));
                    mma_f16(acc[hh][f][0], acc[hh][f][1], acc[hh][f][2], acc[hh][f][3],
                            a0, a1, a2, a3, b0, b1);
                }
            }
        }
        // no trailing barrier: sync1 of next iteration orders PV before aS/eB overwrite
    }

    #pragma unroll
    for (int hh = 0; hh < 6; hh++) {
        const int h = wg * 6 + hh;
        #pragma unroll
        for (int f = 0; f < 2; f++) {
            const long base = ((long)((b << 10) + n0 + f * 16 + r8)) * PC + h * 64 + w8 * 8 + c4 * 2;
            *(__half2*)(oh + base)           = __floats2half2_rn(acc[hh][f][0], acc[hh][f][1]);
            *(__half2*)(oh + base + 8L * PC) = __floats2half2_rn(acc[hh][f][2], acc[hh][f][3]);
        }
    }
}

// ---------------- launcher ----------------
extern "C" void kernel_launch(void* const* d_in, const int* in_sizes, int n_in,
                              void* d_out, int out_size)
{
    const float* x      = (const float*)d_in[0];
    const float* W_qkv  = (const float*)d_in[1];
    const float* W_proj = (const float*)d_in[2];
    const float* b_proj = (const float*)d_in[3];
    const float* W_l    = (const float*)d_in[4];
    const float* b_l    = (const float*)d_in[5];
    const float* W_w    = (const float*)d_in[6];
    const float* b_w    = (const float*)d_in[7];
    const float* lamb   = (const float*)d_in[8];
    float* out = (float*)d_out;

    __half *xh, *wqh, *wph, *qh, *kh, *vh, *e, *oh;
    float *rs;
    cudaGetSymbolAddress((void**)&xh,  g_xh);
    cudaGetSymbolAddress((void**)&wqh, g_wqh);
    cudaGetSymbolAddress((void**)&wph, g_wph);
    cudaGetSymbolAddress((void**)&qh,  g_qh);
    cudaGetSymbolAddress((void**)&kh,  g_kh);
    cudaGetSymbolAddress((void**)&vh,  g_vh);
    cudaGetSymbolAddress((void**)&e,   g_e);
    cudaGetSymbolAddress((void**)&rs,  g_rs);
    cudaGetSymbolAddress((void**)&oh,  g_oh);

    const int M = PB * PN;
    constexpr int SM_G = 3 * 2 * 128 * 72 * 2;   // 110592 (BK=64, 3 stages)

    {   const int total = N4_X + N4_WQ + N4_WP;
        f2h_all<<<(total + 255) / 256, 256>>>(x, W_qkv, W_proj, xh, wqh, wph);
    }
    {   auto kfn = gemm_h<128, 128, 64, 3, 2>;
        cudaFuncSetAttribute(kfn, cudaFuncAttributeMaxDynamicSharedMemorySize, SM_G);
        dim3 grid(3 * PC / 128, M / 128, 1);
        kfn<<<grid, 256, SM_G>>>(xh, wqh, nullptr, nullptr, M, 3 * PC, PC, 0, qh, kh, vh);
    }
    {   cudaFuncSetAttribute(qk_exp, cudaFuncAttributeMaxDynamicSharedMemorySize, S1_SM);
        dim3 grid(PN / 32, PB, 1);
        qk_exp<<<grid, 256, S1_SM>>>(qh, kh, e, rs, W_l, b_l);
    }
    {   cudaFuncSetAttribute(mix_pv, cudaFuncAttributeMaxDynamicSharedMemorySize, S6_SM);
        dim3 grid(PN / 32, PB, 1);
        mix_pv<<<grid, 512, S6_SM>>>(e, vh, rs, oh, W_w, b_w, lamb);
    }
    {   auto kfn = gemm_h<128, 128, 64, 3, 0>;
        cudaFuncSetAttribute(kfn, cudaFuncAttributeMaxDynamicSharedMemorySize, SM_G);
        dim3 grid(PC / 128, M / 128, 1);
        kfn<<<grid, 256, SM_G>>>(oh, wph, out, b_proj, M, PC, PC, PC, nullptr, nullptr, nullptr);
    }
}